// round 3
// baseline (speedup 1.0000x reference)
#include <cuda_runtime.h>
#include <math.h>

// Problem constants: B=1, T=2048, D=1024, H=16, HD=64
#define T_SEQ 2048
#define D_MOD 1024
#define NH    16
#define HDIM  64

// Scratch (allocation-free rule: __device__ globals)
__device__ float g_K[2 * T_SEQ * D_MOD];   // [4096, 1024]  rows 0..2047 from l, 2048..4095 from x
__device__ float g_V[2 * T_SEQ * D_MOD];   // [4096, 1024]
__device__ float g_Q[T_SEQ * D_MOD];       // [2048, 1024]
__device__ float g_Y[T_SEQ * D_MOD];       // [2048, 1024] attention output (pre-proj)

// ---------------------------------------------------------------------------
// SGEMM with bias: out = A[M,1024] @ W[1024,N] + bias[N]
// 128x128 block tile, BK=16, 256 threads, 8x8 micro-tile, register prefetch.
// If out1 != nullptr, columns [0,1024) go to out0, [1024,2048) to out1
// (both with leading dim 1024, row offset rowoff). Otherwise plain store to
// out0 with leading dim 1024 (N is always <= 2048, out ld always 1024).
// ---------------------------------------------------------------------------
__global__ __launch_bounds__(256) void sgemm_bias_kernel(
    const float* __restrict__ A, const float* __restrict__ W,
    const float* __restrict__ bias,
    float* __restrict__ out0, float* __restrict__ out1,
    int N, int rowoff)
{
    const int K = 1024;
    __shared__ float As[16][132];   // transposed A tile, padded
    __shared__ float Bs[16][128];

    int tid = threadIdx.x;
    int tm = tid >> 4, tn = tid & 15;
    int m0 = blockIdx.y << 7, n0 = blockIdx.x << 7;

    // per-thread load coordinates (2 float4 each for A and B per BK step)
    int ar0 = tid >> 2;            // 0..63
    int ar1 = ar0 + 64;            // 64..127
    int ac  = (tid & 3) << 2;      // 0,4,8,12
    int br0 = tid >> 5;            // 0..7
    int br1 = br0 + 8;             // 8..15
    int bc  = (tid & 31) << 2;     // 0..124

    const float* Arow0 = A + (size_t)(m0 + ar0) * K;
    const float* Arow1 = A + (size_t)(m0 + ar1) * K;
    const float* Wcol  = W + n0;

    float acc[8][8];
#pragma unroll
    for (int i = 0; i < 8; i++)
#pragma unroll
        for (int j = 0; j < 8; j++) acc[i][j] = 0.0f;

    float4 pa0 = *(const float4*)(Arow0 + ac);
    float4 pa1 = *(const float4*)(Arow1 + ac);
    float4 pb0 = *(const float4*)(Wcol + (size_t)br0 * N + bc);
    float4 pb1 = *(const float4*)(Wcol + (size_t)br1 * N + bc);

    for (int kt = 0; kt < 64; kt++) {
        // store prefetched tile
        As[ac + 0][ar0] = pa0.x; As[ac + 1][ar0] = pa0.y;
        As[ac + 2][ar0] = pa0.z; As[ac + 3][ar0] = pa0.w;
        As[ac + 0][ar1] = pa1.x; As[ac + 1][ar1] = pa1.y;
        As[ac + 2][ar1] = pa1.z; As[ac + 3][ar1] = pa1.w;
        *(float4*)&Bs[br0][bc] = pb0;
        *(float4*)&Bs[br1][bc] = pb1;
        __syncthreads();

        // prefetch next tile (hidden under compute)
        if (kt < 63) {
            int k0 = (kt + 1) << 4;
            pa0 = *(const float4*)(Arow0 + k0 + ac);
            pa1 = *(const float4*)(Arow1 + k0 + ac);
            pb0 = *(const float4*)(Wcol + (size_t)(k0 + br0) * N + bc);
            pb1 = *(const float4*)(Wcol + (size_t)(k0 + br1) * N + bc);
        }

#pragma unroll
        for (int kk = 0; kk < 16; kk++) {
            float ra[8], rb[8];
            *(float4*)&ra[0] = *(float4*)&As[kk][tm * 8];
            *(float4*)&ra[4] = *(float4*)&As[kk][tm * 8 + 4];
            *(float4*)&rb[0] = *(float4*)&Bs[kk][tn * 8];
            *(float4*)&rb[4] = *(float4*)&Bs[kk][tn * 8 + 4];
#pragma unroll
            for (int i = 0; i < 8; i++)
#pragma unroll
                for (int j = 0; j < 8; j++)
                    acc[i][j] = fmaf(ra[i], rb[j], acc[i][j]);
        }
        __syncthreads();
    }

    // epilogue: bias + (split) store; output leading dim is always 1024
    float bi[8];
#pragma unroll
    for (int j = 0; j < 8; j++) bi[j] = bias[n0 + tn * 8 + j];

    float* dst = out0;
    int cb = n0 + tn * 8;
    if (out1 != nullptr && n0 >= 1024) { dst = out1; cb -= 1024; }

#pragma unroll
    for (int i = 0; i < 8; i++) {
        size_t row = (size_t)(rowoff + m0 + tm * 8 + i);
#pragma unroll
        for (int jj = 0; jj < 2; jj++) {
            float4 v;
            v.x = acc[i][jj * 4 + 0] + bi[jj * 4 + 0];
            v.y = acc[i][jj * 4 + 1] + bi[jj * 4 + 1];
            v.z = acc[i][jj * 4 + 2] + bi[jj * 4 + 2];
            v.w = acc[i][jj * 4 + 3] + bi[jj * 4 + 3];
            *(float4*)&dst[row * 1024 + cb + jj * 4] = v;
        }
    }
}

// ---------------------------------------------------------------------------
// Flash attention, fp32. Block = (query block of 64, head). 256 threads as
// 16x16; each thread owns a 4x4 patch of S/P and a 4(row)x4(dcol) patch of O.
// K length 4096; mask: key s valid iff s < q_global + 2048. Exactly one
// triangular tile per query block at s0 = q0 + 2048 (local rule: j < r).
// ---------------------------------------------------------------------------
#define AT_PAD 68  // float stride, keeps 16B alignment (68*4=272)

__global__ __launch_bounds__(256) void attn_kernel(
    const float* __restrict__ Q, const float* __restrict__ K,
    const float* __restrict__ V, float* __restrict__ Y)
{
    extern __shared__ float sm[];
    float* Qst = sm;                      // [64][AT_PAD]  Qst[d][r]
    float* Kst = sm + 64 * AT_PAD;        // [64][AT_PAD]  Kst[d][j]
    float* Vs  = sm + 2 * 64 * AT_PAD;    // [64][AT_PAD]  Vs[j][d]
    float* Ps  = sm + 3 * 64 * AT_PAD;    // [64][AT_PAD]  Ps[r][j]

    int tid = threadIdx.x;
    int ty = tid >> 4, tx = tid & 15;
    int h  = blockIdx.y;
    int q0 = blockIdx.x << 6;
    int col0 = h * HDIM;

    // load Q tile, transposed store (once per block)
#pragma unroll
    for (int it = 0; it < 4; it++) {
        int lin = tid + it * 256;          // 0..1023
        int r = lin >> 4;
        int d4 = (lin & 15) << 2;
        float4 qv = *(const float4*)&Q[(size_t)(q0 + r) * D_MOD + col0 + d4];
        Qst[(d4 + 0) * AT_PAD + r] = qv.x;
        Qst[(d4 + 1) * AT_PAD + r] = qv.y;
        Qst[(d4 + 2) * AT_PAD + r] = qv.z;
        Qst[(d4 + 3) * AT_PAD + r] = qv.w;
    }

    float O[4][4];
    float mrow[4], lrow[4];
#pragma unroll
    for (int i = 0; i < 4; i++) {
        mrow[i] = -INFINITY; lrow[i] = 0.0f;
#pragma unroll
        for (int c = 0; c < 4; c++) O[i][c] = 0.0f;
    }

    int ntiles = (2048 + q0) / 64 + 1;     // 33..64
    for (int t = 0; t < ntiles; t++) {
        int s0 = t << 6;
        __syncthreads();   // protect smem reuse from previous tile; covers Q stores at t=0

        // load K (transposed) and V (natural)
#pragma unroll
        for (int it = 0; it < 4; it++) {
            int lin = tid + it * 256;
            int j = lin >> 4;
            int d4 = (lin & 15) << 2;
            float4 kv = *(const float4*)&K[(size_t)(s0 + j) * D_MOD + col0 + d4];
            Kst[(d4 + 0) * AT_PAD + j] = kv.x;
            Kst[(d4 + 1) * AT_PAD + j] = kv.y;
            Kst[(d4 + 2) * AT_PAD + j] = kv.z;
            Kst[(d4 + 3) * AT_PAD + j] = kv.w;
            float4 vv = *(const float4*)&V[(size_t)(s0 + j) * D_MOD + col0 + d4];
            *(float4*)&Vs[j * AT_PAD + d4] = vv;
        }
        __syncthreads();

        // S = Q K^T (4x4 per thread)
        float S[4][4];
#pragma unroll
        for (int i = 0; i < 4; i++)
#pragma unroll
            for (int j = 0; j < 4; j++) S[i][j] = 0.0f;

#pragma unroll 8
        for (int d = 0; d < 64; d++) {
            float qa[4], kb[4];
            *(float4*)&qa[0] = *(float4*)&Qst[d * AT_PAD + ty * 4];
            *(float4*)&kb[0] = *(float4*)&Kst[d * AT_PAD + tx * 4];
#pragma unroll
            for (int i = 0; i < 4; i++)
#pragma unroll
                for (int j = 0; j < 4; j++)
                    S[i][j] = fmaf(qa[i], kb[j], S[i][j]);
        }

        const float scale = 0.125f;   // 1/sqrt(64)
        bool diag = (s0 == q0 + 2048);
#pragma unroll
        for (int i = 0; i < 4; i++)
#pragma unroll
            for (int j = 0; j < 4; j++) {
                S[i][j] *= scale;
                if (diag && (tx * 4 + j) >= (ty * 4 + i)) S[i][j] = -1e30f;
            }

        // row max (reduce across tx = low 4 lane bits)
        float rm[4];
#pragma unroll
        for (int i = 0; i < 4; i++) {
            rm[i] = fmaxf(fmaxf(S[i][0], S[i][1]), fmaxf(S[i][2], S[i][3]));
        }
#pragma unroll
        for (int msk = 1; msk <= 8; msk <<= 1)
#pragma unroll
            for (int i = 0; i < 4; i++)
                rm[i] = fmaxf(rm[i], __shfl_xor_sync(0xffffffffu, rm[i], msk));

        float alpha[4];
#pragma unroll
        for (int i = 0; i < 4; i++) {
            float mn = fmaxf(mrow[i], rm[i]);
            alpha[i] = __expf(mrow[i] - mn);
            mrow[i] = mn;
        }

        // P = exp(S - m), row sums, store P
        float rs[4];
#pragma unroll
        for (int i = 0; i < 4; i++) {
            rs[i] = 0.0f;
#pragma unroll
            for (int j = 0; j < 4; j++) {
                float p = __expf(S[i][j] - mrow[i]);
                Ps[(ty * 4 + i) * AT_PAD + tx * 4 + j] = p;
                rs[i] += p;
            }
        }
#pragma unroll
        for (int msk = 1; msk <= 8; msk <<= 1)
#pragma unroll
            for (int i = 0; i < 4; i++)
                rs[i] += __shfl_xor_sync(0xffffffffu, rs[i], msk);

#pragma unroll
        for (int i = 0; i < 4; i++) {
            lrow[i] = lrow[i] * alpha[i] + rs[i];
#pragma unroll
            for (int c = 0; c < 4; c++) O[i][c] *= alpha[i];
        }
        __syncthreads();   // P visible to all before PV

        // O += P V
#pragma unroll 8
        for (int j = 0; j < 64; j++) {
            float vv[4];
            *(float4*)&vv[0] = *(float4*)&Vs[j * AT_PAD + tx * 4];
            float pr[4];
#pragma unroll
            for (int i = 0; i < 4; i++) pr[i] = Ps[(ty * 4 + i) * AT_PAD + j];
#pragma unroll
            for (int i = 0; i < 4; i++)
#pragma unroll
                for (int c = 0; c < 4; c++)
                    O[i][c] = fmaf(pr[i], vv[c], O[i][c]);
        }
    }

    // normalize + store
#pragma unroll
    for (int i = 0; i < 4; i++) {
        float inv = 1.0f / lrow[i];
        float4 o;
        o.x = O[i][0] * inv; o.y = O[i][1] * inv;
        o.z = O[i][2] * inv; o.w = O[i][3] * inv;
        *(float4*)&Y[(size_t)(q0 + ty * 4 + i) * D_MOD + col0 + tx * 4] = o;
    }
}

// ---------------------------------------------------------------------------
extern "C" void kernel_launch(void* const* d_in, const int* in_sizes, int n_in,
                              void* d_out, int out_size)
{
    (void)in_sizes; (void)n_in; (void)out_size;
    const float* l        = (const float*)d_in[0];
    const float* x        = (const float*)d_in[1];
    const float* W_attn_l = (const float*)d_in[2];
    const float* b_attn_l = (const float*)d_in[3];
    const float* W_attn_c = (const float*)d_in[4];
    const float* b_attn_c = (const float*)d_in[5];
    const float* W_q      = (const float*)d_in[6];
    const float* b_q      = (const float*)d_in[7];
    const float* W_proj   = (const float*)d_in[8];
    const float* b_proj   = (const float*)d_in[9];
    float* out = (float*)d_out;

    float *Kp, *Vp, *Qp, *Yp;
    cudaGetSymbolAddress((void**)&Kp, g_K);
    cudaGetSymbolAddress((void**)&Vp, g_V);
    cudaGetSymbolAddress((void**)&Qp, g_Q);
    cudaGetSymbolAddress((void**)&Yp, g_Y);

    dim3 blk(256);

    // kv_l -> K[0:2048], V[0:2048]; kv_c -> K[2048:4096], V[2048:4096]
    sgemm_bias_kernel<<<dim3(16, 16), blk>>>(l, W_attn_l, b_attn_l, Kp, Vp, 2048, 0);
    sgemm_bias_kernel<<<dim3(16, 16), blk>>>(x, W_attn_c, b_attn_c, Kp, Vp, 2048, 2048);
    // q
    sgemm_bias_kernel<<<dim3(8, 16), blk>>>(x, W_q, b_q, Qp, nullptr, 1024, 0);

    // attention
    size_t smem = 4 * 64 * AT_PAD * sizeof(float);   // 69632 B
    cudaFuncSetAttribute(attn_kernel, cudaFuncAttributeMaxDynamicSharedMemorySize, (int)smem);
    attn_kernel<<<dim3(32, 16), blk, smem>>>(Qp, Kp, Vp, Yp);

    // output projection
    sgemm_bias_kernel<<<dim3(8, 16), blk>>>(Yp, W_proj, b_proj, out, nullptr, 1024, 0);
}

// round 5
// speedup vs baseline: 1.3117x; 1.3117x over previous
#include <cuda_runtime.h>
#include <math.h>
#include <stdint.h>

// Problem constants: B=1, T=2048, D=1024, H=16, HD=64
#define T_SEQ 2048
#define D_MOD 1024
#define NH    16
#define HDIM  64

// Scratch (allocation-free rule: __device__ globals)
__device__ float g_K[2 * T_SEQ * D_MOD];   // [4096, 1024]
__device__ float g_V[2 * T_SEQ * D_MOD];   // [4096, 1024]
__device__ float g_Q[T_SEQ * D_MOD];       // [2048, 1024]
__device__ float g_Y[T_SEQ * D_MOD];       // [2048, 1024]

// ---------------------------------------------------------------------------
// tf32 helpers
// ---------------------------------------------------------------------------
__device__ __forceinline__ float to_tf32(float f) {
    uint32_t u;
    asm("cvt.rna.tf32.f32 %0, %1;" : "=r"(u) : "f"(f));
    return __uint_as_float(u);
}

__device__ __forceinline__ void mma_tf32(float* c,
    uint32_t a0, uint32_t a1, uint32_t a2, uint32_t a3,
    uint32_t b0, uint32_t b1)
{
    asm volatile(
        "mma.sync.aligned.m16n8k8.row.col.f32.tf32.tf32.f32 "
        "{%0,%1,%2,%3}, {%4,%5,%6,%7}, {%8,%9}, {%0,%1,%2,%3};\n"
        : "+f"(c[0]), "+f"(c[1]), "+f"(c[2]), "+f"(c[3])
        : "r"(a0), "r"(a1), "r"(a2), "r"(a3), "r"(b0), "r"(b1));
}

// ---------------------------------------------------------------------------
// tf32 tensor-core GEMM with bias: out = A[M,1024] @ W[1024,N] + bias[N]
// 128x128 block tile, BK=32, 256 threads = 8 warps (2x4), warp tile 64x32.
// mma.sync m16n8k8 tf32; operands rounded via cvt.rna at smem store.
// Split-store: if out1 != nullptr, cols [0,1024) -> out0, [1024,2048) -> out1
// (both ld 1024, row offset rowoff).
// ---------------------------------------------------------------------------
#define AS_STRIDE 36    // 128 rows x 32 cols, padded: bank = (4g+t)%32, conflict-free
#define BS_STRIDE 136   // 32 rows x 128 cols, padded: bank = (8t+g)%32, conflict-free

__global__ __launch_bounds__(256) void gemm_tf32_bias_kernel(
    const float* __restrict__ A, const float* __restrict__ W,
    const float* __restrict__ bias,
    float* __restrict__ out0, float* __restrict__ out1,
    int N, int rowoff)
{
    __shared__ float As[128 * AS_STRIDE];   // [m][k] padded
    __shared__ float Bs[32 * BS_STRIDE];    // [k][n] padded

    const int tid  = threadIdx.x;
    const int wid  = tid >> 5;
    const int lane = tid & 31;
    const int g    = lane >> 2;   // 0..7
    const int t    = lane & 3;    // 0..3
    const int warp_m = wid >> 2;  // 0..1
    const int warp_n = wid & 3;   // 0..3

    const int m0 = blockIdx.y << 7;
    const int n0 = blockIdx.x << 7;

    // loader coordinates (4 float4 per array per iteration)
    int ar[4], ac[4], br[4], bc[4];
#pragma unroll
    for (int i = 0; i < 4; i++) {
        int lin = tid + (i << 8);
        ar[i] = lin >> 3;          // 0..127
        ac[i] = (lin & 7) << 2;    // 0..28
        br[i] = lin >> 5;          // 0..31
        bc[i] = (lin & 31) << 2;   // 0..124
    }

    float acc[4][4][4];
#pragma unroll
    for (int fm = 0; fm < 4; fm++)
#pragma unroll
        for (int fn = 0; fn < 4; fn++)
#pragma unroll
            for (int e = 0; e < 4; e++) acc[fm][fn][e] = 0.0f;

    // prefetch first K-tile
    float4 pa[4], pb[4];
#pragma unroll
    for (int i = 0; i < 4; i++) {
        pa[i] = *(const float4*)&A[(size_t)(m0 + ar[i]) * 1024 + ac[i]];
        pb[i] = *(const float4*)&W[(size_t)br[i] * N + n0 + bc[i]];
    }

    for (int kt = 0; kt < 32; kt++) {
        // store prefetched tile (tf32-rounded)
#pragma unroll
        for (int i = 0; i < 4; i++) {
            float* pdst = &As[ar[i] * AS_STRIDE + ac[i]];
            pdst[0] = to_tf32(pa[i].x); pdst[1] = to_tf32(pa[i].y);
            pdst[2] = to_tf32(pa[i].z); pdst[3] = to_tf32(pa[i].w);
            float* qdst = &Bs[br[i] * BS_STRIDE + bc[i]];
            qdst[0] = to_tf32(pb[i].x); qdst[1] = to_tf32(pb[i].y);
            qdst[2] = to_tf32(pb[i].z); qdst[3] = to_tf32(pb[i].w);
        }
        __syncthreads();

        // prefetch next K-tile
        if (kt < 31) {
            int k0 = (kt + 1) << 5;
#pragma unroll
            for (int i = 0; i < 4; i++) {
                pa[i] = *(const float4*)&A[(size_t)(m0 + ar[i]) * 1024 + k0 + ac[i]];
                pb[i] = *(const float4*)&W[(size_t)(k0 + br[i]) * N + n0 + bc[i]];
            }
        }

        // 4 k-steps of 8
#pragma unroll
        for (int ks = 0; ks < 4; ks++) {
            int k0 = ks << 3;
            uint32_t b0[4], b1[4];
#pragma unroll
            for (int fn = 0; fn < 4; fn++) {
                int nb = warp_n * 32 + fn * 8 + g;
                b0[fn] = __float_as_uint(Bs[(k0 + t) * BS_STRIDE + nb]);
                b1[fn] = __float_as_uint(Bs[(k0 + t + 4) * BS_STRIDE + nb]);
            }
#pragma unroll
            for (int fm = 0; fm < 4; fm++) {
                int mr = warp_m * 64 + fm * 16 + g;
                uint32_t a0 = __float_as_uint(As[mr * AS_STRIDE + k0 + t]);
                uint32_t a1 = __float_as_uint(As[(mr + 8) * AS_STRIDE + k0 + t]);
                uint32_t a2 = __float_as_uint(As[mr * AS_STRIDE + k0 + 4 + t]);
                uint32_t a3 = __float_as_uint(As[(mr + 8) * AS_STRIDE + k0 + 4 + t]);
#pragma unroll
                for (int fn = 0; fn < 4; fn++)
                    mma_tf32(acc[fm][fn], a0, a1, a2, a3, b0[fn], b1[fn]);
            }
        }
        __syncthreads();
    }

    // epilogue: bias + split store (float2 per fragment half)
#pragma unroll
    for (int fm = 0; fm < 4; fm++) {
        int row = m0 + warp_m * 64 + fm * 16 + g;
#pragma unroll
        for (int fn = 0; fn < 4; fn++) {
            int col = n0 + warp_n * 32 + fn * 8 + 2 * t;
            float bx = bias[col], by = bias[col + 1];
            float* dst = out0;
            int c = col;
            if (out1 != nullptr && col >= 1024) { dst = out1; c = col - 1024; }
            float2 v0 = make_float2(acc[fm][fn][0] + bx, acc[fm][fn][1] + by);
            float2 v1 = make_float2(acc[fm][fn][2] + bx, acc[fm][fn][3] + by);
            *(float2*)&dst[(size_t)(rowoff + row) * 1024 + c] = v0;
            *(float2*)&dst[(size_t)(rowoff + row + 8) * 1024 + c] = v1;
        }
    }
}

// ---------------------------------------------------------------------------
// Flash attention, fp32 (unchanged from measured-good R3 kernel).
// ---------------------------------------------------------------------------
#define AT_PAD 68

__global__ __launch_bounds__(256) void attn_kernel(
    const float* __restrict__ Q, const float* __restrict__ K,
    const float* __restrict__ V, float* __restrict__ Y)
{
    extern __shared__ float sm[];
    float* Qst = sm;                      // [64][AT_PAD]  Qst[d][r]
    float* Kst = sm + 64 * AT_PAD;        // [64][AT_PAD]  Kst[d][j]
    float* Vs  = sm + 2 * 64 * AT_PAD;    // [64][AT_PAD]  Vs[j][d]
    float* Ps  = sm + 3 * 64 * AT_PAD;    // [64][AT_PAD]  Ps[r][j]

    int tid = threadIdx.x;
    int ty = tid >> 4, tx = tid & 15;
    int h  = blockIdx.y;
    int q0 = blockIdx.x << 6;
    int col0 = h * HDIM;

#pragma unroll
    for (int it = 0; it < 4; it++) {
        int lin = tid + it * 256;
        int r = lin >> 4;
        int d4 = (lin & 15) << 2;
        float4 qv = *(const float4*)&Q[(size_t)(q0 + r) * D_MOD + col0 + d4];
        Qst[(d4 + 0) * AT_PAD + r] = qv.x;
        Qst[(d4 + 1) * AT_PAD + r] = qv.y;
        Qst[(d4 + 2) * AT_PAD + r] = qv.z;
        Qst[(d4 + 3) * AT_PAD + r] = qv.w;
    }

    float O[4][4];
    float mrow[4], lrow[4];
#pragma unroll
    for (int i = 0; i < 4; i++) {
        mrow[i] = -INFINITY; lrow[i] = 0.0f;
#pragma unroll
        for (int c = 0; c < 4; c++) O[i][c] = 0.0f;
    }

    int ntiles = (2048 + q0) / 64 + 1;
    for (int t = 0; t < ntiles; t++) {
        int s0 = t << 6;
        __syncthreads();

#pragma unroll
        for (int it = 0; it < 4; it++) {
            int lin = tid + it * 256;
            int j = lin >> 4;
            int d4 = (lin & 15) << 2;
            float4 kv = *(const float4*)&K[(size_t)(s0 + j) * D_MOD + col0 + d4];
            Kst[(d4 + 0) * AT_PAD + j] = kv.x;
            Kst[(d4 + 1) * AT_PAD + j] = kv.y;
            Kst[(d4 + 2) * AT_PAD + j] = kv.z;
            Kst[(d4 + 3) * AT_PAD + j] = kv.w;
            float4 vv = *(const float4*)&V[(size_t)(s0 + j) * D_MOD + col0 + d4];
            *(float4*)&Vs[j * AT_PAD + d4] = vv;
        }
        __syncthreads();

        float S[4][4];
#pragma unroll
        for (int i = 0; i < 4; i++)
#pragma unroll
            for (int j = 0; j < 4; j++) S[i][j] = 0.0f;

#pragma unroll 8
        for (int d = 0; d < 64; d++) {
            float qa[4], kb[4];
            *(float4*)&qa[0] = *(float4*)&Qst[d * AT_PAD + ty * 4];
            *(float4*)&kb[0] = *(float4*)&Kst[d * AT_PAD + tx * 4];
#pragma unroll
            for (int i = 0; i < 4; i++)
#pragma unroll
                for (int j = 0; j < 4; j++)
                    S[i][j] = fmaf(qa[i], kb[j], S[i][j]);
        }

        const float scale = 0.125f;
        bool diag = (s0 == q0 + 2048);
#pragma unroll
        for (int i = 0; i < 4; i++)
#pragma unroll
            for (int j = 0; j < 4; j++) {
                S[i][j] *= scale;
                if (diag && (tx * 4 + j) >= (ty * 4 + i)) S[i][j] = -1e30f;
            }

        float rm[4];
#pragma unroll
        for (int i = 0; i < 4; i++)
            rm[i] = fmaxf(fmaxf(S[i][0], S[i][1]), fmaxf(S[i][2], S[i][3]));
#pragma unroll
        for (int msk = 1; msk <= 8; msk <<= 1)
#pragma unroll
            for (int i = 0; i < 4; i++)
                rm[i] = fmaxf(rm[i], __shfl_xor_sync(0xffffffffu, rm[i], msk));

        float alpha[4];
#pragma unroll
        for (int i = 0; i < 4; i++) {
            float mn = fmaxf(mrow[i], rm[i]);
            alpha[i] = __expf(mrow[i] - mn);
            mrow[i] = mn;
        }

        float rs[4];
#pragma unroll
        for (int i = 0; i < 4; i++) {
            rs[i] = 0.0f;
#pragma unroll
            for (int j = 0; j < 4; j++) {
                float p = __expf(S[i][j] - mrow[i]);
                Ps[(ty * 4 + i) * AT_PAD + tx * 4 + j] = p;
                rs[i] += p;
            }
        }
#pragma unroll
        for (int msk = 1; msk <= 8; msk <<= 1)
#pragma unroll
            for (int i = 0; i < 4; i++)
                rs[i] += __shfl_xor_sync(0xffffffffu, rs[i], msk);

#pragma unroll
        for (int i = 0; i < 4; i++) {
            lrow[i] = lrow[i] * alpha[i] + rs[i];
#pragma unroll
            for (int c = 0; c < 4; c++) O[i][c] *= alpha[i];
        }
        __syncthreads();

#pragma unroll 8
        for (int j = 0; j < 64; j++) {
            float vv[4];
            *(float4*)&vv[0] = *(float4*)&Vs[j * AT_PAD + tx * 4];
            float pr[4];
#pragma unroll
            for (int i = 0; i < 4; i++) pr[i] = Ps[(ty * 4 + i) * AT_PAD + j];
#pragma unroll
            for (int i = 0; i < 4; i++)
#pragma unroll
                for (int c = 0; c < 4; c++)
                    O[i][c] = fmaf(pr[i], vv[c], O[i][c]);
        }
    }

#pragma unroll
    for (int i = 0; i < 4; i++) {
        float inv = 1.0f / lrow[i];
        float4 o;
        o.x = O[i][0] * inv; o.y = O[i][1] * inv;
        o.z = O[i][2] * inv; o.w = O[i][3] * inv;
        *(float4*)&Y[(size_t)(q0 + ty * 4 + i) * D_MOD + col0 + tx * 4] = o;
    }
}

// ---------------------------------------------------------------------------
extern "C" void kernel_launch(void* const* d_in, const int* in_sizes, int n_in,
                              void* d_out, int out_size)
{
    (void)in_sizes; (void)n_in; (void)out_size;
    const float* l        = (const float*)d_in[0];
    const float* x        = (const float*)d_in[1];
    const float* W_attn_l = (const float*)d_in[2];
    const float* b_attn_l = (const float*)d_in[3];
    const float* W_attn_c = (const float*)d_in[4];
    const float* b_attn_c = (const float*)d_in[5];
    const float* W_q      = (const float*)d_in[6];
    const float* b_q      = (const float*)d_in[7];
    const float* W_proj   = (const float*)d_in[8];
    const float* b_proj   = (const float*)d_in[9];
    float* out = (float*)d_out;

    float *Kp, *Vp, *Qp, *Yp;
    cudaGetSymbolAddress((void**)&Kp, g_K);
    cudaGetSymbolAddress((void**)&Vp, g_V);
    cudaGetSymbolAddress((void**)&Qp, g_Q);
    cudaGetSymbolAddress((void**)&Yp, g_Y);

    dim3 blk(256);

    // kv_l -> K[0:2048], V[0:2048]; kv_c -> K[2048:4096], V[2048:4096]
    gemm_tf32_bias_kernel<<<dim3(16, 16), blk>>>(l, W_attn_l, b_attn_l, Kp, Vp, 2048, 0);
    gemm_tf32_bias_kernel<<<dim3(16, 16), blk>>>(x, W_attn_c, b_attn_c, Kp, Vp, 2048, 2048);
    // q
    gemm_tf32_bias_kernel<<<dim3(8, 16), blk>>>(x, W_q, b_q, Qp, nullptr, 1024, 0);

    // attention
    size_t smem = 4 * 64 * AT_PAD * sizeof(float);   // 69632 B
    cudaFuncSetAttribute(attn_kernel, cudaFuncAttributeMaxDynamicSharedMemorySize, (int)smem);
    attn_kernel<<<dim3(32, 16), blk, smem>>>(Qp, Kp, Vp, Yp);

    // output projection
    gemm_tf32_bias_kernel<<<dim3(8, 16), blk>>>(Yp, W_proj, b_proj, out, nullptr, 1024, 0);
}

// round 6
// speedup vs baseline: 1.5650x; 1.1931x over previous
#include <cuda_runtime.h>
#include <math.h>
#include <stdint.h>

// Problem constants: B=1, T=2048, D=1024, H=16, HD=64
#define T_SEQ 2048
#define D_MOD 1024
#define NH    16
#define HDIM  64

// Scratch (allocation-free rule: __device__ globals)
__device__ float g_K[2 * T_SEQ * D_MOD];   // [4096, 1024]
__device__ float g_V[2 * T_SEQ * D_MOD];   // [4096, 1024]
__device__ float g_Q[T_SEQ * D_MOD];       // [2048, 1024]
__device__ float g_Y[T_SEQ * D_MOD];       // [2048, 1024]

// ---------------------------------------------------------------------------
// tf32 helpers
// ---------------------------------------------------------------------------
__device__ __forceinline__ float to_tf32(float f) {
    uint32_t u;
    asm("cvt.rna.tf32.f32 %0, %1;" : "=r"(u) : "f"(f));
    return __uint_as_float(u);
}

__device__ __forceinline__ void split_tf32(float x, uint32_t& hi, uint32_t& lo) {
    uint32_t h;
    asm("cvt.rna.tf32.f32 %0, %1;" : "=r"(h) : "f"(x));
    float r = x - __uint_as_float(h);
    uint32_t l;
    asm("cvt.rna.tf32.f32 %0, %1;" : "=r"(l) : "f"(r));
    hi = h; lo = l;
}

__device__ __forceinline__ void mma_tf32(float* c,
    uint32_t a0, uint32_t a1, uint32_t a2, uint32_t a3,
    uint32_t b0, uint32_t b1)
{
    asm volatile(
        "mma.sync.aligned.m16n8k8.row.col.f32.tf32.tf32.f32 "
        "{%0,%1,%2,%3}, {%4,%5,%6,%7}, {%8,%9}, {%0,%1,%2,%3};\n"
        : "+f"(c[0]), "+f"(c[1]), "+f"(c[2]), "+f"(c[3])
        : "r"(a0), "r"(a1), "r"(a2), "r"(a3), "r"(b0), "r"(b1));
}

// ---------------------------------------------------------------------------
// tf32 tensor-core GEMM with bias (unchanged, measured-good R5 kernel)
// ---------------------------------------------------------------------------
#define AS_STRIDE 36
#define BS_STRIDE 136

__global__ __launch_bounds__(256) void gemm_tf32_bias_kernel(
    const float* __restrict__ A, const float* __restrict__ W,
    const float* __restrict__ bias,
    float* __restrict__ out0, float* __restrict__ out1,
    int N, int rowoff)
{
    __shared__ float As[128 * AS_STRIDE];
    __shared__ float Bs[32 * BS_STRIDE];

    const int tid  = threadIdx.x;
    const int wid  = tid >> 5;
    const int lane = tid & 31;
    const int g    = lane >> 2;
    const int t    = lane & 3;
    const int warp_m = wid >> 2;
    const int warp_n = wid & 3;

    const int m0 = blockIdx.y << 7;
    const int n0 = blockIdx.x << 7;

    int ar[4], ac[4], br[4], bc[4];
#pragma unroll
    for (int i = 0; i < 4; i++) {
        int lin = tid + (i << 8);
        ar[i] = lin >> 3;
        ac[i] = (lin & 7) << 2;
        br[i] = lin >> 5;
        bc[i] = (lin & 31) << 2;
    }

    float acc[4][4][4];
#pragma unroll
    for (int fm = 0; fm < 4; fm++)
#pragma unroll
        for (int fn = 0; fn < 4; fn++)
#pragma unroll
            for (int e = 0; e < 4; e++) acc[fm][fn][e] = 0.0f;

    float4 pa[4], pb[4];
#pragma unroll
    for (int i = 0; i < 4; i++) {
        pa[i] = *(const float4*)&A[(size_t)(m0 + ar[i]) * 1024 + ac[i]];
        pb[i] = *(const float4*)&W[(size_t)br[i] * N + n0 + bc[i]];
    }

    for (int kt = 0; kt < 32; kt++) {
#pragma unroll
        for (int i = 0; i < 4; i++) {
            float* pdst = &As[ar[i] * AS_STRIDE + ac[i]];
            pdst[0] = to_tf32(pa[i].x); pdst[1] = to_tf32(pa[i].y);
            pdst[2] = to_tf32(pa[i].z); pdst[3] = to_tf32(pa[i].w);
            float* qdst = &Bs[br[i] * BS_STRIDE + bc[i]];
            qdst[0] = to_tf32(pb[i].x); qdst[1] = to_tf32(pb[i].y);
            qdst[2] = to_tf32(pb[i].z); qdst[3] = to_tf32(pb[i].w);
        }
        __syncthreads();

        if (kt < 31) {
            int k0 = (kt + 1) << 5;
#pragma unroll
            for (int i = 0; i < 4; i++) {
                pa[i] = *(const float4*)&A[(size_t)(m0 + ar[i]) * 1024 + k0 + ac[i]];
                pb[i] = *(const float4*)&W[(size_t)(k0 + br[i]) * N + n0 + bc[i]];
            }
        }

#pragma unroll
        for (int ks = 0; ks < 4; ks++) {
            int k0 = ks << 3;
            uint32_t b0[4], b1[4];
#pragma unroll
            for (int fn = 0; fn < 4; fn++) {
                int nb = warp_n * 32 + fn * 8 + g;
                b0[fn] = __float_as_uint(Bs[(k0 + t) * BS_STRIDE + nb]);
                b1[fn] = __float_as_uint(Bs[(k0 + t + 4) * BS_STRIDE + nb]);
            }
#pragma unroll
            for (int fm = 0; fm < 4; fm++) {
                int mr = warp_m * 64 + fm * 16 + g;
                uint32_t a0 = __float_as_uint(As[mr * AS_STRIDE + k0 + t]);
                uint32_t a1 = __float_as_uint(As[(mr + 8) * AS_STRIDE + k0 + t]);
                uint32_t a2 = __float_as_uint(As[mr * AS_STRIDE + k0 + 4 + t]);
                uint32_t a3 = __float_as_uint(As[(mr + 8) * AS_STRIDE + k0 + 4 + t]);
#pragma unroll
                for (int fn = 0; fn < 4; fn++)
                    mma_tf32(acc[fm][fn], a0, a1, a2, a3, b0[fn], b1[fn]);
            }
        }
        __syncthreads();
    }

#pragma unroll
    for (int fm = 0; fm < 4; fm++) {
        int row = m0 + warp_m * 64 + fm * 16 + g;
#pragma unroll
        for (int fn = 0; fn < 4; fn++) {
            int col = n0 + warp_n * 32 + fn * 8 + 2 * t;
            float bx = bias[col], by = bias[col + 1];
            float* dst = out0;
            int c = col;
            if (out1 != nullptr && col >= 1024) { dst = out1; c = col - 1024; }
            float2 v0 = make_float2(acc[fm][fn][0] + bx, acc[fm][fn][1] + by);
            float2 v1 = make_float2(acc[fm][fn][2] + bx, acc[fm][fn][3] + by);
            *(float2*)&dst[(size_t)(rowoff + row) * 1024 + c] = v0;
            *(float2*)&dst[(size_t)(rowoff + row + 8) * 1024 + c] = v1;
        }
    }
}

// ---------------------------------------------------------------------------
// Tensor-core flash attention (tf32 mma with hi/lo split = near-fp32 accuracy)
// Block: 128 queries x 1 head, 256 threads = 8 warps.
// Each warp owns 16 complete query rows (m16), all 64 keys (8 n-fragments).
// K tile = 64 keys. S = QK^T and O += PV each use 3-mma splits (drop lo*lo).
// Softmax is warp-local (shfl over lane bits 0-1); P is warp-private smem.
// smem layout (floats, stride 68):
//   Qs [128][68] row-major  Kst [64][68] d-major  Vs [64][68] j-major  Ps [128][68]
// ---------------------------------------------------------------------------
#define AP 68

__global__ __launch_bounds__(256, 1) void attn_mma_kernel(
    const float* __restrict__ Q, const float* __restrict__ K,
    const float* __restrict__ V, float* __restrict__ Y)
{
    extern __shared__ float sm[];
    float* Qs  = sm;                    // [128][AP]
    float* Kst = sm + 128 * AP;         // [64][AP]  Kst[d][j]
    float* Vs  = Kst + 64 * AP;         // [64][AP]  Vs[j][d]
    float* Ps  = Vs + 64 * AP;          // [128][AP]

    const int tid  = threadIdx.x;
    const int wid  = tid >> 5;
    const int lane = tid & 31;
    const int g    = lane >> 2;   // 0..7
    const int t    = lane & 3;    // 0..3

    const int h  = blockIdx.y;
    const int qb = blockIdx.x;
    const int q0 = qb << 7;           // 128 queries per block
    const int col0 = h * HDIM;

    const int row0 = wid * 16 + g;    // this thread's 2 rows: row0, row0+8

    // ---- load Q tile [128][64] (row-major, float4) ----
#pragma unroll
    for (int it = 0; it < 8; it++) {
        int lin = tid + (it << 8);     // 0..2047
        int r = lin >> 4;
        int d4 = (lin & 15) << 2;
        float4 qv = *(const float4*)&Q[(size_t)(q0 + r) * D_MOD + col0 + d4];
        *(float4*)&Qs[r * AP + d4] = qv;
    }

    float O[8][4];
#pragma unroll
    for (int fn = 0; fn < 8; fn++)
#pragma unroll
        for (int e = 0; e < 4; e++) O[fn][e] = 0.0f;
    float m0 = -INFINITY, m1 = -INFINITY, l0 = 0.0f, l1 = 0.0f;

    const int ntiles = (q0 >> 6) + 34;   // covers keys up to q0+127+2047

    for (int tt = 0; tt < ntiles; tt++) {
        int s0 = tt << 6;
        __syncthreads();

        // ---- load K (transposed -> Kst[d][j]) and V (natural) ----
#pragma unroll
        for (int it = 0; it < 4; it++) {
            int lin = tid + (it << 8);  // 0..1023
            int j = lin >> 4;
            int d4 = (lin & 15) << 2;
            float4 kv = *(const float4*)&K[(size_t)(s0 + j) * D_MOD + col0 + d4];
            Kst[(d4 + 0) * AP + j] = kv.x;
            Kst[(d4 + 1) * AP + j] = kv.y;
            Kst[(d4 + 2) * AP + j] = kv.z;
            Kst[(d4 + 3) * AP + j] = kv.w;
            float4 vv = *(const float4*)&V[(size_t)(s0 + j) * D_MOD + col0 + d4];
            *(float4*)&Vs[j * AP + d4] = vv;
        }
        __syncthreads();

        // ---- S = Q K^T via split tf32 mma ----
        float sacc[8][4];
#pragma unroll
        for (int fn = 0; fn < 8; fn++)
#pragma unroll
            for (int e = 0; e < 4; e++) sacc[fn][e] = 0.0f;

#pragma unroll
        for (int ks = 0; ks < 8; ks++) {
            int k0 = ks << 3;
            uint32_t ah0, al0, ah1, al1, ah2, al2, ah3, al3;
            split_tf32(Qs[row0 * AP + k0 + t],           ah0, al0);
            split_tf32(Qs[(row0 + 8) * AP + k0 + t],     ah1, al1);
            split_tf32(Qs[row0 * AP + k0 + t + 4],       ah2, al2);
            split_tf32(Qs[(row0 + 8) * AP + k0 + t + 4], ah3, al3);
#pragma unroll
            for (int fn = 0; fn < 8; fn++) {
                uint32_t bh0, bl0, bh1, bl1;
                split_tf32(Kst[(k0 + t) * AP + fn * 8 + g],     bh0, bl0);
                split_tf32(Kst[(k0 + t + 4) * AP + fn * 8 + g], bh1, bl1);
                mma_tf32(sacc[fn], ah0, ah1, ah2, ah3, bh0, bh1);
                mma_tf32(sacc[fn], ah0, ah1, ah2, ah3, bl0, bl1);
                mma_tf32(sacc[fn], al0, al1, al2, al3, bh0, bh1);
            }
        }

        // ---- scale + mask ----
        const float scale = 0.125f;
        bool bnd = (s0 + 63 >= q0 + 2048);
#pragma unroll
        for (int fn = 0; fn < 8; fn++) {
#pragma unroll
            for (int e = 0; e < 4; e++) {
                float s = sacc[fn][e] * scale;
                if (bnd) {
                    int col = fn * 8 + 2 * t + (e & 1);
                    int rw  = (e < 2) ? row0 : row0 + 8;
                    if (s0 + col >= q0 + rw + 2048) s = -1e30f;
                }
                sacc[fn][e] = s;
            }
        }

        // ---- row max (warp-local: reduce over t via shfl xor 1,2) ----
        float rm0 = -INFINITY, rm1 = -INFINITY;
#pragma unroll
        for (int fn = 0; fn < 8; fn++) {
            rm0 = fmaxf(rm0, fmaxf(sacc[fn][0], sacc[fn][1]));
            rm1 = fmaxf(rm1, fmaxf(sacc[fn][2], sacc[fn][3]));
        }
        rm0 = fmaxf(rm0, __shfl_xor_sync(0xffffffffu, rm0, 1));
        rm0 = fmaxf(rm0, __shfl_xor_sync(0xffffffffu, rm0, 2));
        rm1 = fmaxf(rm1, __shfl_xor_sync(0xffffffffu, rm1, 1));
        rm1 = fmaxf(rm1, __shfl_xor_sync(0xffffffffu, rm1, 2));

        float mn0 = fmaxf(m0, rm0), mn1 = fmaxf(m1, rm1);
        float a0 = __expf(m0 - mn0), a1 = __expf(m1 - mn1);
        m0 = mn0; m1 = mn1;

        // ---- P = exp(S - m), row sums, store P (warp-private) ----
        float rs0 = 0.0f, rs1 = 0.0f;
#pragma unroll
        for (int fn = 0; fn < 8; fn++) {
            float p0 = __expf(sacc[fn][0] - m0);
            float p1 = __expf(sacc[fn][1] - m0);
            float p2 = __expf(sacc[fn][2] - m1);
            float p3 = __expf(sacc[fn][3] - m1);
            rs0 += p0 + p1; rs1 += p2 + p3;
            *(float2*)&Ps[row0 * AP + fn * 8 + 2 * t]       = make_float2(p0, p1);
            *(float2*)&Ps[(row0 + 8) * AP + fn * 8 + 2 * t] = make_float2(p2, p3);
        }
        rs0 += __shfl_xor_sync(0xffffffffu, rs0, 1);
        rs0 += __shfl_xor_sync(0xffffffffu, rs0, 2);
        rs1 += __shfl_xor_sync(0xffffffffu, rs1, 1);
        rs1 += __shfl_xor_sync(0xffffffffu, rs1, 2);
        l0 = l0 * a0 + rs0;
        l1 = l1 * a1 + rs1;

#pragma unroll
        for (int fn = 0; fn < 8; fn++) {
            O[fn][0] *= a0; O[fn][1] *= a0;
            O[fn][2] *= a1; O[fn][3] *= a1;
        }
        __syncwarp();   // P rows are warp-private: warp-level sync suffices

        // ---- O += P V via split tf32 mma ----
#pragma unroll
        for (int ks = 0; ks < 8; ks++) {
            int k0 = ks << 3;
            uint32_t ph0, pl0, ph1, pl1, ph2, pl2, ph3, pl3;
            split_tf32(Ps[row0 * AP + k0 + t],           ph0, pl0);
            split_tf32(Ps[(row0 + 8) * AP + k0 + t],     ph1, pl1);
            split_tf32(Ps[row0 * AP + k0 + t + 4],       ph2, pl2);
            split_tf32(Ps[(row0 + 8) * AP + k0 + t + 4], ph3, pl3);
#pragma unroll
            for (int fn = 0; fn < 8; fn++) {
                uint32_t vh0, vl0, vh1, vl1;
                split_tf32(Vs[(k0 + t) * AP + fn * 8 + g],     vh0, vl0);
                split_tf32(Vs[(k0 + t + 4) * AP + fn * 8 + g], vh1, vl1);
                mma_tf32(O[fn], ph0, ph1, ph2, ph3, vh0, vh1);
                mma_tf32(O[fn], ph0, ph1, ph2, ph3, vl0, vl1);
                mma_tf32(O[fn], pl0, pl1, pl2, pl3, vh0, vh1);
            }
        }
        __syncwarp();   // done reading Ps/Vs before next-tile overwrite (block sync at loop top)
    }

    // ---- normalize + store ----
    float inv0 = 1.0f / l0, inv1 = 1.0f / l1;
#pragma unroll
    for (int fn = 0; fn < 8; fn++) {
        int col = col0 + fn * 8 + 2 * t;
        *(float2*)&Y[(size_t)(q0 + row0) * D_MOD + col] =
            make_float2(O[fn][0] * inv0, O[fn][1] * inv0);
        *(float2*)&Y[(size_t)(q0 + row0 + 8) * D_MOD + col] =
            make_float2(O[fn][2] * inv1, O[fn][3] * inv1);
    }
}

// ---------------------------------------------------------------------------
extern "C" void kernel_launch(void* const* d_in, const int* in_sizes, int n_in,
                              void* d_out, int out_size)
{
    (void)in_sizes; (void)n_in; (void)out_size;
    const float* l        = (const float*)d_in[0];
    const float* x        = (const float*)d_in[1];
    const float* W_attn_l = (const float*)d_in[2];
    const float* b_attn_l = (const float*)d_in[3];
    const float* W_attn_c = (const float*)d_in[4];
    const float* b_attn_c = (const float*)d_in[5];
    const float* W_q      = (const float*)d_in[6];
    const float* b_q      = (const float*)d_in[7];
    const float* W_proj   = (const float*)d_in[8];
    const float* b_proj   = (const float*)d_in[9];
    float* out = (float*)d_out;

    float *Kp, *Vp, *Qp, *Yp;
    cudaGetSymbolAddress((void**)&Kp, g_K);
    cudaGetSymbolAddress((void**)&Vp, g_V);
    cudaGetSymbolAddress((void**)&Qp, g_Q);
    cudaGetSymbolAddress((void**)&Yp, g_Y);

    dim3 blk(256);

    // kv_l -> K[0:2048], V[0:2048]; kv_c -> K[2048:4096], V[2048:4096]
    gemm_tf32_bias_kernel<<<dim3(16, 16), blk>>>(l, W_attn_l, b_attn_l, Kp, Vp, 2048, 0);
    gemm_tf32_bias_kernel<<<dim3(16, 16), blk>>>(x, W_attn_c, b_attn_c, Kp, Vp, 2048, 2048);
    // q
    gemm_tf32_bias_kernel<<<dim3(8, 16), blk>>>(x, W_q, b_q, Qp, nullptr, 1024, 0);

    // attention: 16 q-blocks of 128, 16 heads
    size_t smem = (size_t)(128 + 64 + 64 + 128) * AP * sizeof(float);   // 104448 B
    cudaFuncSetAttribute(attn_mma_kernel, cudaFuncAttributeMaxDynamicSharedMemorySize, (int)smem);
    attn_mma_kernel<<<dim3(16, 16), blk, smem>>>(Qp, Kp, Vp, Yp);

    // output projection
    gemm_tf32_bias_kernel<<<dim3(8, 16), blk>>>(Yp, W_proj, b_proj, out, nullptr, 1024, 0);
}

// round 9
// speedup vs baseline: 1.7502x; 1.1183x over previous
#include <cuda_runtime.h>
#include <math.h>
#include <stdint.h>

// Problem constants: B=1, T=2048, D=1024, H=16, HD=64
#define T_SEQ 2048
#define D_MOD 1024
#define NH    16
#define HDIM  64

// Scratch (allocation-free rule: __device__ globals)
__device__ float g_K[2 * T_SEQ * D_MOD];   // [4096, 1024]
__device__ float g_V[2 * T_SEQ * D_MOD];   // [4096, 1024]
__device__ float g_Q[T_SEQ * D_MOD];       // [2048, 1024]
__device__ float g_Y[T_SEQ * D_MOD];       // [2048, 1024]

// ---------------------------------------------------------------------------
// tf32 helpers
// ---------------------------------------------------------------------------
__device__ __forceinline__ float to_tf32(float f) {
    uint32_t u;
    asm("cvt.rna.tf32.f32 %0, %1;" : "=r"(u) : "f"(f));
    return __uint_as_float(u);
}

__device__ __forceinline__ void split_tf32(float x, uint32_t& hi, uint32_t& lo) {
    uint32_t h;
    asm("cvt.rna.tf32.f32 %0, %1;" : "=r"(h) : "f"(x));
    float r = x - __uint_as_float(h);
    uint32_t l;
    asm("cvt.rna.tf32.f32 %0, %1;" : "=r"(l) : "f"(r));
    hi = h; lo = l;
}

__device__ __forceinline__ void mma_tf32(float* c,
    uint32_t a0, uint32_t a1, uint32_t a2, uint32_t a3,
    uint32_t b0, uint32_t b1)
{
    asm volatile(
        "mma.sync.aligned.m16n8k8.row.col.f32.tf32.tf32.f32 "
        "{%0,%1,%2,%3}, {%4,%5,%6,%7}, {%8,%9}, {%0,%1,%2,%3};\n"
        : "+f"(c[0]), "+f"(c[1]), "+f"(c[2]), "+f"(c[3])
        : "r"(a0), "r"(a1), "r"(a2), "r"(a3), "r"(b0), "r"(b1));
}

// ---------------------------------------------------------------------------
// tf32 tensor-core GEMM with bias (unchanged, measured-good R5 kernel)
// ---------------------------------------------------------------------------
#define AS_STRIDE 36
#define BS_STRIDE 136

__global__ __launch_bounds__(256) void gemm_tf32_bias_kernel(
    const float* __restrict__ A, const float* __restrict__ W,
    const float* __restrict__ bias,
    float* __restrict__ out0, float* __restrict__ out1,
    int N, int rowoff)
{
    __shared__ float As[128 * AS_STRIDE];
    __shared__ float Bs[32 * BS_STRIDE];

    const int tid  = threadIdx.x;
    const int wid  = tid >> 5;
    const int lane = tid & 31;
    const int g    = lane >> 2;
    const int t    = lane & 3;
    const int warp_m = wid >> 2;
    const int warp_n = wid & 3;

    const int m0 = blockIdx.y << 7;
    const int n0 = blockIdx.x << 7;

    int ar[4], ac[4], br[4], bc[4];
#pragma unroll
    for (int i = 0; i < 4; i++) {
        int lin = tid + (i << 8);
        ar[i] = lin >> 3;
        ac[i] = (lin & 7) << 2;
        br[i] = lin >> 5;
        bc[i] = (lin & 31) << 2;
    }

    float acc[4][4][4];
#pragma unroll
    for (int fm = 0; fm < 4; fm++)
#pragma unroll
        for (int fn = 0; fn < 4; fn++)
#pragma unroll
            for (int e = 0; e < 4; e++) acc[fm][fn][e] = 0.0f;

    float4 pa[4], pb[4];
#pragma unroll
    for (int i = 0; i < 4; i++) {
        pa[i] = *(const float4*)&A[(size_t)(m0 + ar[i]) * 1024 + ac[i]];
        pb[i] = *(const float4*)&W[(size_t)br[i] * N + n0 + bc[i]];
    }

    for (int kt = 0; kt < 32; kt++) {
#pragma unroll
        for (int i = 0; i < 4; i++) {
            float* pdst = &As[ar[i] * AS_STRIDE + ac[i]];
            pdst[0] = to_tf32(pa[i].x); pdst[1] = to_tf32(pa[i].y);
            pdst[2] = to_tf32(pa[i].z); pdst[3] = to_tf32(pa[i].w);
            float* qdst = &Bs[br[i] * BS_STRIDE + bc[i]];
            qdst[0] = to_tf32(pb[i].x); qdst[1] = to_tf32(pb[i].y);
            qdst[2] = to_tf32(pb[i].z); qdst[3] = to_tf32(pb[i].w);
        }
        __syncthreads();

        if (kt < 31) {
            int k0 = (kt + 1) << 5;
#pragma unroll
            for (int i = 0; i < 4; i++) {
                pa[i] = *(const float4*)&A[(size_t)(m0 + ar[i]) * 1024 + k0 + ac[i]];
                pb[i] = *(const float4*)&W[(size_t)(k0 + br[i]) * N + n0 + bc[i]];
            }
        }

#pragma unroll
        for (int ks = 0; ks < 4; ks++) {
            int k0 = ks << 3;
            uint32_t b0[4], b1[4];
#pragma unroll
            for (int fn = 0; fn < 4; fn++) {
                int nb = warp_n * 32 + fn * 8 + g;
                b0[fn] = __float_as_uint(Bs[(k0 + t) * BS_STRIDE + nb]);
                b1[fn] = __float_as_uint(Bs[(k0 + t + 4) * BS_STRIDE + nb]);
            }
#pragma unroll
            for (int fm = 0; fm < 4; fm++) {
                int mr = warp_m * 64 + fm * 16 + g;
                uint32_t a0 = __float_as_uint(As[mr * AS_STRIDE + k0 + t]);
                uint32_t a1 = __float_as_uint(As[(mr + 8) * AS_STRIDE + k0 + t]);
                uint32_t a2 = __float_as_uint(As[mr * AS_STRIDE + k0 + 4 + t]);
                uint32_t a3 = __float_as_uint(As[(mr + 8) * AS_STRIDE + k0 + 4 + t]);
#pragma unroll
                for (int fn = 0; fn < 4; fn++)
                    mma_tf32(acc[fm][fn], a0, a1, a2, a3, b0[fn], b1[fn]);
            }
        }
        __syncthreads();
    }

#pragma unroll
    for (int fm = 0; fm < 4; fm++) {
        int row = m0 + warp_m * 64 + fm * 16 + g;
#pragma unroll
        for (int fn = 0; fn < 4; fn++) {
            int col = n0 + warp_n * 32 + fn * 8 + 2 * t;
            float bx = bias[col], by = bias[col + 1];
            float* dst = out0;
            int c = col;
            if (out1 != nullptr && col >= 1024) { dst = out1; c = col - 1024; }
            float2 v0 = make_float2(acc[fm][fn][0] + bx, acc[fm][fn][1] + by);
            float2 v1 = make_float2(acc[fm][fn][2] + bx, acc[fm][fn][3] + by);
            *(float2*)&dst[(size_t)(rowoff + row) * 1024 + c] = v0;
            *(float2*)&dst[(size_t)(rowoff + row + 8) * 1024 + c] = v1;
        }
    }
}

// ---------------------------------------------------------------------------
// Tensor-core flash attention v2.
// Changes vs v1 (numerically identical):
//  - K and V stored in smem as interleaved (hi,lo) float2, split ONCE at tile
//    load by all 256 threads; mma B-fragment gather = single LDS.64, no ALU.
//  - P matrix never goes to smem: PV A-fragments fetched from the producing
//    lanes' registers via __shfl_sync (pure intra-warp permutation).
// Block: 128 queries x 1 head, 256 threads = 8 warps; warp owns 16 rows.
// smem = Qs fp32 [128][68] + Ks2/Vs2 float2 [64][68] = 104448 B -> 2 CTA/SM.
// ---------------------------------------------------------------------------
#define QP  68   // Q fp32 stride (floats)
#define KP2 68   // K/V float2 stride (float2 units)

__global__ __launch_bounds__(256, 2) void attn_mma_kernel(
    const float* __restrict__ Q, const float* __restrict__ K,
    const float* __restrict__ V, float* __restrict__ Y)
{
    extern __shared__ float sm[];
    float*  Qs  = sm;                            // [128][QP]
    float2* Ks2 = (float2*)(sm + 128 * QP);      // [64 j][KP2 d] (hi,lo)
    float2* Vs2 = Ks2 + 64 * KP2;                // [64 j][KP2 d] (hi,lo)

    const int tid  = threadIdx.x;
    const int wid  = tid >> 5;
    const int lane = tid & 31;
    const int g    = lane >> 2;   // 0..7
    const int t    = lane & 3;    // 0..3

    const int h  = blockIdx.y;
    const int q0 = blockIdx.x << 7;
    const int col0 = h * HDIM;

    const int row0 = wid * 16 + g;

    // shfl source lanes for PV A-fragment permutation
    const int srcA = (lane & 0x1C) | (t >> 1);   // holds col k0+t
    const int srcB = srcA + 2;                   // holds col k0+t+4
    const bool todd = (t & 1);

    // ---- load Q tile [128][64] ----
#pragma unroll
    for (int it = 0; it < 8; it++) {
        int lin = tid + (it << 8);
        int r = lin >> 4;
        int d4 = (lin & 15) << 2;
        float4 qv = *(const float4*)&Q[(size_t)(q0 + r) * D_MOD + col0 + d4];
        *(float4*)&Qs[r * QP + d4] = qv;
    }

    float O[8][4];
#pragma unroll
    for (int fn = 0; fn < 8; fn++)
#pragma unroll
        for (int e = 0; e < 4; e++) O[fn][e] = 0.0f;
    float m0 = -INFINITY, m1 = -INFINITY, l0 = 0.0f, l1 = 0.0f;

    const int ntiles = (q0 >> 6) + 34;

    for (int tt = 0; tt < ntiles; tt++) {
        int s0 = tt << 6;
        __syncthreads();

        // ---- load K/V tile, split to (hi,lo) float2, vectorized stores ----
#pragma unroll
        for (int it = 0; it < 4; it++) {
            int lin = tid + (it << 8);  // 0..1023
            int j = lin >> 4;
            int d4 = (lin & 15) << 2;
            float4 kv = *(const float4*)&K[(size_t)(s0 + j) * D_MOD + col0 + d4];
            uint32_t hx, lx, hy, ly, hz, lz, hw, lw;
            split_tf32(kv.x, hx, lx); split_tf32(kv.y, hy, ly);
            split_tf32(kv.z, hz, lz); split_tf32(kv.w, hw, lw);
            float2* kd = &Ks2[j * KP2 + d4];
            *(float4*)kd = make_float4(__uint_as_float(hx), __uint_as_float(lx),
                                       __uint_as_float(hy), __uint_as_float(ly));
            *(float4*)(kd + 2) = make_float4(__uint_as_float(hz), __uint_as_float(lz),
                                             __uint_as_float(hw), __uint_as_float(lw));
            float4 vv = *(const float4*)&V[(size_t)(s0 + j) * D_MOD + col0 + d4];
            split_tf32(vv.x, hx, lx); split_tf32(vv.y, hy, ly);
            split_tf32(vv.z, hz, lz); split_tf32(vv.w, hw, lw);
            float2* vd = &Vs2[j * KP2 + d4];
            *(float4*)vd = make_float4(__uint_as_float(hx), __uint_as_float(lx),
                                       __uint_as_float(hy), __uint_as_float(ly));
            *(float4*)(vd + 2) = make_float4(__uint_as_float(hz), __uint_as_float(lz),
                                             __uint_as_float(hw), __uint_as_float(lw));
        }
        __syncthreads();

        // ---- S = Q K^T via split tf32 mma (3 mmas, lo*lo dropped) ----
        float sacc[8][4];
#pragma unroll
        for (int fn = 0; fn < 8; fn++)
#pragma unroll
            for (int e = 0; e < 4; e++) sacc[fn][e] = 0.0f;

#pragma unroll
        for (int ks = 0; ks < 8; ks++) {
            int k0 = ks << 3;
            uint32_t ah0, al0, ah1, al1, ah2, al2, ah3, al3;
            split_tf32(Qs[row0 * QP + k0 + t],           ah0, al0);
            split_tf32(Qs[(row0 + 8) * QP + k0 + t],     ah1, al1);
            split_tf32(Qs[row0 * QP + k0 + t + 4],       ah2, al2);
            split_tf32(Qs[(row0 + 8) * QP + k0 + t + 4], ah3, al3);
#pragma unroll
            for (int fn = 0; fn < 8; fn++) {
                float2 b0 = Ks2[(fn * 8 + g) * KP2 + k0 + t];
                float2 b1 = Ks2[(fn * 8 + g) * KP2 + k0 + t + 4];
                uint32_t bh0 = __float_as_uint(b0.x), bl0 = __float_as_uint(b0.y);
                uint32_t bh1 = __float_as_uint(b1.x), bl1 = __float_as_uint(b1.y);
                mma_tf32(sacc[fn], ah0, ah1, ah2, ah3, bh0, bh1);
                mma_tf32(sacc[fn], ah0, ah1, ah2, ah3, bl0, bl1);
                mma_tf32(sacc[fn], al0, al1, al2, al3, bh0, bh1);
            }
        }

        // ---- scale + mask ----
        const float scale = 0.125f;
        bool bnd = (s0 + 63 >= q0 + 2048);
#pragma unroll
        for (int fn = 0; fn < 8; fn++) {
#pragma unroll
            for (int e = 0; e < 4; e++) {
                float s = sacc[fn][e] * scale;
                if (bnd) {
                    int col = fn * 8 + 2 * t + (e & 1);
                    int rw  = (e < 2) ? row0 : row0 + 8;
                    if (s0 + col >= q0 + rw + 2048) s = -1e30f;
                }
                sacc[fn][e] = s;
            }
        }

        // ---- row max (warp-local over t: shfl xor 1,2) ----
        float rm0 = -INFINITY, rm1 = -INFINITY;
#pragma unroll
        for (int fn = 0; fn < 8; fn++) {
            rm0 = fmaxf(rm0, fmaxf(sacc[fn][0], sacc[fn][1]));
            rm1 = fmaxf(rm1, fmaxf(sacc[fn][2], sacc[fn][3]));
        }
        rm0 = fmaxf(rm0, __shfl_xor_sync(0xffffffffu, rm0, 1));
        rm0 = fmaxf(rm0, __shfl_xor_sync(0xffffffffu, rm0, 2));
        rm1 = fmaxf(rm1, __shfl_xor_sync(0xffffffffu, rm1, 1));
        rm1 = fmaxf(rm1, __shfl_xor_sync(0xffffffffu, rm1, 2));

        float mn0 = fmaxf(m0, rm0), mn1 = fmaxf(m1, rm1);
        float a0 = __expf(m0 - mn0), a1 = __expf(m1 - mn1);
        m0 = mn0; m1 = mn1;

        // ---- P = exp(S - m) in place, row sums ----
        float rs0 = 0.0f, rs1 = 0.0f;
#pragma unroll
        for (int fn = 0; fn < 8; fn++) {
            float p0 = __expf(sacc[fn][0] - m0);
            float p1 = __expf(sacc[fn][1] - m0);
            float p2 = __expf(sacc[fn][2] - m1);
            float p3 = __expf(sacc[fn][3] - m1);
            sacc[fn][0] = p0; sacc[fn][1] = p1;
            sacc[fn][2] = p2; sacc[fn][3] = p3;
            rs0 += p0 + p1; rs1 += p2 + p3;
        }
        rs0 += __shfl_xor_sync(0xffffffffu, rs0, 1);
        rs0 += __shfl_xor_sync(0xffffffffu, rs0, 2);
        rs1 += __shfl_xor_sync(0xffffffffu, rs1, 1);
        rs1 += __shfl_xor_sync(0xffffffffu, rs1, 2);
        l0 = l0 * a0 + rs0;
        l1 = l1 * a1 + rs1;

#pragma unroll
        for (int fn = 0; fn < 8; fn++) {
            O[fn][0] *= a0; O[fn][1] *= a0;
            O[fn][2] *= a1; O[fn][3] *= a1;
        }

        // ---- O += P V: A-fragments via intra-warp shfl of sacc regs ----
#pragma unroll
        for (int ks = 0; ks < 8; ks++) {
            int k0 = ks << 3;
            float s00 = __shfl_sync(0xffffffffu, sacc[ks][0], srcA);
            float s01 = __shfl_sync(0xffffffffu, sacc[ks][1], srcA);
            float s02 = __shfl_sync(0xffffffffu, sacc[ks][2], srcA);
            float s03 = __shfl_sync(0xffffffffu, sacc[ks][3], srcA);
            float u00 = __shfl_sync(0xffffffffu, sacc[ks][0], srcB);
            float u01 = __shfl_sync(0xffffffffu, sacc[ks][1], srcB);
            float u02 = __shfl_sync(0xffffffffu, sacc[ks][2], srcB);
            float u03 = __shfl_sync(0xffffffffu, sacc[ks][3], srcB);
            float a0f = todd ? s01 : s00;
            float a1f = todd ? s03 : s02;
            float a2f = todd ? u01 : u00;
            float a3f = todd ? u03 : u02;
            uint32_t ph0, pl0, ph1, pl1, ph2, pl2, ph3, pl3;
            split_tf32(a0f, ph0, pl0);
            split_tf32(a1f, ph1, pl1);
            split_tf32(a2f, ph2, pl2);
            split_tf32(a3f, ph3, pl3);
#pragma unroll
            for (int fn = 0; fn < 8; fn++) {
                float2 v0 = Vs2[(k0 + t) * KP2 + fn * 8 + g];
                float2 v1 = Vs2[(k0 + t + 4) * KP2 + fn * 8 + g];
                uint32_t vh0 = __float_as_uint(v0.x), vl0 = __float_as_uint(v0.y);
                uint32_t vh1 = __float_as_uint(v1.x), vl1 = __float_as_uint(v1.y);
                mma_tf32(O[fn], ph0, ph1, ph2, ph3, vh0, vh1);
                mma_tf32(O[fn], ph0, ph1, ph2, ph3, vl0, vl1);
                mma_tf32(O[fn], pl0, pl1, pl2, pl3, vh0, vh1);
            }
        }
    }

    // ---- normalize + store ----
    float inv0 = 1.0f / l0, inv1 = 1.0f / l1;
#pragma unroll
    for (int fn = 0; fn < 8; fn++) {
        int col = col0 + fn * 8 + 2 * t;
        *(float2*)&Y[(size_t)(q0 + row0) * D_MOD + col] =
            make_float2(O[fn][0] * inv0, O[fn][1] * inv0);
        *(float2*)&Y[(size_t)(q0 + row0 + 8) * D_MOD + col] =
            make_float2(O[fn][2] * inv1, O[fn][3] * inv1);
    }
}

// ---------------------------------------------------------------------------
extern "C" void kernel_launch(void* const* d_in, const int* in_sizes, int n_in,
                              void* d_out, int out_size)
{
    (void)in_sizes; (void)n_in; (void)out_size;
    const float* l        = (const float*)d_in[0];
    const float* x        = (const float*)d_in[1];
    const float* W_attn_l = (const float*)d_in[2];
    const float* b_attn_l = (const float*)d_in[3];
    const float* W_attn_c = (const float*)d_in[4];
    const float* b_attn_c = (const float*)d_in[5];
    const float* W_q      = (const float*)d_in[6];
    const float* b_q      = (const float*)d_in[7];
    const float* W_proj   = (const float*)d_in[8];
    const float* b_proj   = (const float*)d_in[9];
    float* out = (float*)d_out;

    float *Kp, *Vp, *Qp, *Yp;
    cudaGetSymbolAddress((void**)&Kp, g_K);
    cudaGetSymbolAddress((void**)&Vp, g_V);
    cudaGetSymbolAddress((void**)&Qp, g_Q);
    cudaGetSymbolAddress((void**)&Yp, g_Y);

    dim3 blk(256);

    gemm_tf32_bias_kernel<<<dim3(16, 16), blk>>>(l, W_attn_l, b_attn_l, Kp, Vp, 2048, 0);
    gemm_tf32_bias_kernel<<<dim3(16, 16), blk>>>(x, W_attn_c, b_attn_c, Kp, Vp, 2048, 2048);
    gemm_tf32_bias_kernel<<<dim3(8, 16), blk>>>(x, W_q, b_q, Qp, nullptr, 1024, 0);

    // attention: 16 q-blocks of 128, 16 heads; smem = 104448 B (2 CTA/SM)
    size_t smem = (size_t)(128 * QP) * sizeof(float)      // Qs
                + (size_t)(2 * 64 * KP2) * sizeof(float2); // Ks2 + Vs2
    cudaFuncSetAttribute(attn_mma_kernel, cudaFuncAttributeMaxDynamicSharedMemorySize, (int)smem);
    attn_mma_kernel<<<dim3(16, 16), blk, smem>>>(Qp, Kp, Vp, Yp);

    gemm_tf32_bias_kernel<<<dim3(8, 16), blk>>>(Yp, W_proj, b_proj, out, nullptr, 1024, 0);
}

// round 10
// speedup vs baseline: 2.3619x; 1.3495x over previous
#include <cuda_runtime.h>
#include <cuda_bf16.h>
#include <math.h>
#include <stdint.h>

// Problem constants: B=1, T=2048, D=1024, H=16, HD=64
#define T_SEQ 2048
#define D_MOD 1024
#define NH    16
#define HDIM  64

// Scratch (allocation-free rule: __device__ globals)
__device__ float g_K[2 * T_SEQ * D_MOD];   // [4096, 1024]
__device__ float g_V[2 * T_SEQ * D_MOD];   // [4096, 1024]
__device__ float g_Q[T_SEQ * D_MOD];       // [2048, 1024]
__device__ float g_Y[T_SEQ * D_MOD];       // [2048, 1024]

// ---------------------------------------------------------------------------
// helpers
// ---------------------------------------------------------------------------
__device__ __forceinline__ float to_tf32(float f) {
    uint32_t u;
    asm("cvt.rna.tf32.f32 %0, %1;" : "=r"(u) : "f"(f));
    return __uint_as_float(u);
}

__device__ __forceinline__ void mma_tf32(float* c,
    uint32_t a0, uint32_t a1, uint32_t a2, uint32_t a3,
    uint32_t b0, uint32_t b1)
{
    asm volatile(
        "mma.sync.aligned.m16n8k8.row.col.f32.tf32.tf32.f32 "
        "{%0,%1,%2,%3}, {%4,%5,%6,%7}, {%8,%9}, {%0,%1,%2,%3};\n"
        : "+f"(c[0]), "+f"(c[1]), "+f"(c[2]), "+f"(c[3])
        : "r"(a0), "r"(a1), "r"(a2), "r"(a3), "r"(b0), "r"(b1));
}

__device__ __forceinline__ void mma_bf16(float* c,
    uint32_t a0, uint32_t a1, uint32_t a2, uint32_t a3,
    uint32_t b0, uint32_t b1)
{
    asm volatile(
        "mma.sync.aligned.m16n8k16.row.col.f32.bf16.bf16.f32 "
        "{%0,%1,%2,%3}, {%4,%5,%6,%7}, {%8,%9}, {%0,%1,%2,%3};\n"
        : "+f"(c[0]), "+f"(c[1]), "+f"(c[2]), "+f"(c[3])
        : "r"(a0), "r"(a1), "r"(a2), "r"(a3), "r"(b0), "r"(b1));
}

__device__ __forceinline__ void bsplit(float x, __nv_bfloat16& h, __nv_bfloat16& l) {
    h = __float2bfloat16(x);
    l = __float2bfloat16(x - __bfloat162float(h));
}

__device__ __forceinline__ uint32_t bpack(__nv_bfloat16 lo, __nv_bfloat16 hi) {
    __nv_bfloat162 p = __halves2bfloat162(lo, hi);   // lo -> bits[0:16)
    return *(uint32_t*)&p;
}

// ---------------------------------------------------------------------------
// tf32 tensor-core GEMM with bias (unchanged, measured-good R5 kernel)
// ---------------------------------------------------------------------------
#define AS_STRIDE 36
#define BS_STRIDE 136

__global__ __launch_bounds__(256) void gemm_tf32_bias_kernel(
    const float* __restrict__ A, const float* __restrict__ W,
    const float* __restrict__ bias,
    float* __restrict__ out0, float* __restrict__ out1,
    int N, int rowoff)
{
    __shared__ float As[128 * AS_STRIDE];
    __shared__ float Bs[32 * BS_STRIDE];

    const int tid  = threadIdx.x;
    const int wid  = tid >> 5;
    const int lane = tid & 31;
    const int g    = lane >> 2;
    const int t    = lane & 3;
    const int warp_m = wid >> 2;
    const int warp_n = wid & 3;

    const int m0 = blockIdx.y << 7;
    const int n0 = blockIdx.x << 7;

    int ar[4], ac[4], br[4], bc[4];
#pragma unroll
    for (int i = 0; i < 4; i++) {
        int lin = tid + (i << 8);
        ar[i] = lin >> 3;
        ac[i] = (lin & 7) << 2;
        br[i] = lin >> 5;
        bc[i] = (lin & 31) << 2;
    }

    float acc[4][4][4];
#pragma unroll
    for (int fm = 0; fm < 4; fm++)
#pragma unroll
        for (int fn = 0; fn < 4; fn++)
#pragma unroll
            for (int e = 0; e < 4; e++) acc[fm][fn][e] = 0.0f;

    float4 pa[4], pb[4];
#pragma unroll
    for (int i = 0; i < 4; i++) {
        pa[i] = *(const float4*)&A[(size_t)(m0 + ar[i]) * 1024 + ac[i]];
        pb[i] = *(const float4*)&W[(size_t)br[i] * N + n0 + bc[i]];
    }

    for (int kt = 0; kt < 32; kt++) {
#pragma unroll
        for (int i = 0; i < 4; i++) {
            float* pdst = &As[ar[i] * AS_STRIDE + ac[i]];
            pdst[0] = to_tf32(pa[i].x); pdst[1] = to_tf32(pa[i].y);
            pdst[2] = to_tf32(pa[i].z); pdst[3] = to_tf32(pa[i].w);
            float* qdst = &Bs[br[i] * BS_STRIDE + bc[i]];
            qdst[0] = to_tf32(pb[i].x); qdst[1] = to_tf32(pb[i].y);
            qdst[2] = to_tf32(pb[i].z); qdst[3] = to_tf32(pb[i].w);
        }
        __syncthreads();

        if (kt < 31) {
            int k0 = (kt + 1) << 5;
#pragma unroll
            for (int i = 0; i < 4; i++) {
                pa[i] = *(const float4*)&A[(size_t)(m0 + ar[i]) * 1024 + k0 + ac[i]];
                pb[i] = *(const float4*)&W[(size_t)(k0 + br[i]) * N + n0 + bc[i]];
            }
        }

#pragma unroll
        for (int ks = 0; ks < 4; ks++) {
            int k0 = ks << 3;
            uint32_t b0[4], b1[4];
#pragma unroll
            for (int fn = 0; fn < 4; fn++) {
                int nb = warp_n * 32 + fn * 8 + g;
                b0[fn] = __float_as_uint(Bs[(k0 + t) * BS_STRIDE + nb]);
                b1[fn] = __float_as_uint(Bs[(k0 + t + 4) * BS_STRIDE + nb]);
            }
#pragma unroll
            for (int fm = 0; fm < 4; fm++) {
                int mr = warp_m * 64 + fm * 16 + g;
                uint32_t a0 = __float_as_uint(As[mr * AS_STRIDE + k0 + t]);
                uint32_t a1 = __float_as_uint(As[(mr + 8) * AS_STRIDE + k0 + t]);
                uint32_t a2 = __float_as_uint(As[mr * AS_STRIDE + k0 + 4 + t]);
                uint32_t a3 = __float_as_uint(As[(mr + 8) * AS_STRIDE + k0 + 4 + t]);
#pragma unroll
                for (int fn = 0; fn < 4; fn++)
                    mma_tf32(acc[fm][fn], a0, a1, a2, a3, b0[fn], b1[fn]);
            }
        }
        __syncthreads();
    }

#pragma unroll
    for (int fm = 0; fm < 4; fm++) {
        int row = m0 + warp_m * 64 + fm * 16 + g;
#pragma unroll
        for (int fn = 0; fn < 4; fn++) {
            int col = n0 + warp_n * 32 + fn * 8 + 2 * t;
            float bx = bias[col], by = bias[col + 1];
            float* dst = out0;
            int c = col;
            if (out1 != nullptr && col >= 1024) { dst = out1; c = col - 1024; }
            float2 v0 = make_float2(acc[fm][fn][0] + bx, acc[fm][fn][1] + by);
            float2 v1 = make_float2(acc[fm][fn][2] + bx, acc[fm][fn][3] + by);
            *(float2*)&dst[(size_t)(rowoff + row) * 1024 + c] = v0;
            *(float2*)&dst[(size_t)(rowoff + row + 8) * 1024 + c] = v1;
        }
    }
}

// ---------------------------------------------------------------------------
// Tensor-core flash attention v3: bf16 m16n8k16 with hi/lo 3-mma split.
//  - Half the tensor instructions of the tf32-k8 version (same MAC count).
//  - Q pre-split to bf16 hi/lo smem ONCE per block (no per-tile Q ALU).
//  - K stored [key][d] bf16 hi/lo; V stored TRANSPOSED [d][key] bf16 hi/lo
//    so all hot-loop fragment gathers are single conflict-free LDS.32
//    (row stride 72 bf16 = 36 words; bank = 4g+t).
//  - PV A-fragment = S-accumulator layout for k16 (a0,a1 = c0..c3 of fn=2ks;
//    a2,a3 = c0..c3 of fn=2ks+1): zero shfl, just bf16x2 packs.
// Block: 128 queries x 1 head, 256 threads = 8 warps; warp owns 16 rows.
// smem = 73728 B.
// ---------------------------------------------------------------------------
#define BSTR 72   // bf16 row stride (72 bf16 = 144 B = 36 words)

__global__ __launch_bounds__(256, 2) void attn_mma_kernel(
    const float* __restrict__ Q, const float* __restrict__ K,
    const float* __restrict__ V, float* __restrict__ Y)
{
    extern __shared__ char smraw[];
    __nv_bfloat16* Qhi = (__nv_bfloat16*)smraw;             // [128][BSTR]
    __nv_bfloat16* Qlo = Qhi + 128 * BSTR;                  // [128][BSTR]
    __nv_bfloat16* Khi = Qlo + 128 * BSTR;                  // [64 key][BSTR d]
    __nv_bfloat16* Klo = Khi + 64 * BSTR;
    __nv_bfloat16* Vthi = Klo + 64 * BSTR;                  // [64 d][BSTR key]
    __nv_bfloat16* Vtlo = Vthi + 64 * BSTR;

    const int tid  = threadIdx.x;
    const int wid  = tid >> 5;
    const int lane = tid & 31;
    const int g    = lane >> 2;   // 0..7
    const int t    = lane & 3;    // 0..3

    const int h  = blockIdx.y;
    const int q0 = blockIdx.x << 7;
    const int col0 = h * HDIM;

    const int row0 = wid * 16 + g;

    // ---- load + pre-split Q tile [128][64] to bf16 hi/lo (once) ----
#pragma unroll
    for (int it = 0; it < 8; it++) {
        int lin = tid + (it << 8);
        int r = lin >> 4;
        int d4 = (lin & 15) << 2;
        float4 qv = *(const float4*)&Q[(size_t)(q0 + r) * D_MOD + col0 + d4];
        __nv_bfloat16 h0, l0b, h1, l1b, h2, l2b, h3, l3b;
        bsplit(qv.x, h0, l0b); bsplit(qv.y, h1, l1b);
        bsplit(qv.z, h2, l2b); bsplit(qv.w, h3, l3b);
        *(uint2*)&Qhi[r * BSTR + d4] = make_uint2(bpack(h0, h1), bpack(h2, h3));
        *(uint2*)&Qlo[r * BSTR + d4] = make_uint2(bpack(l0b, l1b), bpack(l2b, l3b));
    }

    float O[8][4];
#pragma unroll
    for (int fn = 0; fn < 8; fn++)
#pragma unroll
        for (int e = 0; e < 4; e++) O[fn][e] = 0.0f;
    float m0 = -INFINITY, m1 = -INFINITY, l0 = 0.0f, l1 = 0.0f;

    const int ntiles = (q0 >> 6) + 34;

    for (int tt = 0; tt < ntiles; tt++) {
        int s0 = tt << 6;
        __syncthreads();

        // ---- load K/V tile, split to bf16 hi/lo; V stored transposed ----
#pragma unroll
        for (int it = 0; it < 4; it++) {
            int lin = tid + (it << 8);  // 0..1023
            int j = lin >> 4;
            int d4 = (lin & 15) << 2;
            float4 kv = *(const float4*)&K[(size_t)(s0 + j) * D_MOD + col0 + d4];
            __nv_bfloat16 h0, lb0, h1, lb1, h2, lb2, h3, lb3;
            bsplit(kv.x, h0, lb0); bsplit(kv.y, h1, lb1);
            bsplit(kv.z, h2, lb2); bsplit(kv.w, h3, lb3);
            *(uint2*)&Khi[j * BSTR + d4] = make_uint2(bpack(h0, h1), bpack(h2, h3));
            *(uint2*)&Klo[j * BSTR + d4] = make_uint2(bpack(lb0, lb1), bpack(lb2, lb3));
            float4 vv = *(const float4*)&V[(size_t)(s0 + j) * D_MOD + col0 + d4];
            bsplit(vv.x, h0, lb0); bsplit(vv.y, h1, lb1);
            bsplit(vv.z, h2, lb2); bsplit(vv.w, h3, lb3);
            Vthi[(d4 + 0) * BSTR + j] = h0;  Vtlo[(d4 + 0) * BSTR + j] = lb0;
            Vthi[(d4 + 1) * BSTR + j] = h1;  Vtlo[(d4 + 1) * BSTR + j] = lb1;
            Vthi[(d4 + 2) * BSTR + j] = h2;  Vtlo[(d4 + 2) * BSTR + j] = lb2;
            Vthi[(d4 + 3) * BSTR + j] = h3;  Vtlo[(d4 + 3) * BSTR + j] = lb3;
        }
        __syncthreads();

        // ---- S = Q K^T via 3-mma bf16 split (lo*lo dropped) ----
        float sacc[8][4];
#pragma unroll
        for (int fn = 0; fn < 8; fn++)
#pragma unroll
            for (int e = 0; e < 4; e++) sacc[fn][e] = 0.0f;

#pragma unroll
        for (int ks = 0; ks < 4; ks++) {
            int k0 = ks << 4;
            uint32_t ah0 = *(uint32_t*)&Qhi[row0 * BSTR + k0 + 2 * t];
            uint32_t ah1 = *(uint32_t*)&Qhi[(row0 + 8) * BSTR + k0 + 2 * t];
            uint32_t ah2 = *(uint32_t*)&Qhi[row0 * BSTR + k0 + 2 * t + 8];
            uint32_t ah3 = *(uint32_t*)&Qhi[(row0 + 8) * BSTR + k0 + 2 * t + 8];
            uint32_t al0 = *(uint32_t*)&Qlo[row0 * BSTR + k0 + 2 * t];
            uint32_t al1 = *(uint32_t*)&Qlo[(row0 + 8) * BSTR + k0 + 2 * t];
            uint32_t al2 = *(uint32_t*)&Qlo[row0 * BSTR + k0 + 2 * t + 8];
            uint32_t al3 = *(uint32_t*)&Qlo[(row0 + 8) * BSTR + k0 + 2 * t + 8];
#pragma unroll
            for (int fn = 0; fn < 8; fn++) {
                int key = fn * 8 + g;
                uint32_t bh0 = *(uint32_t*)&Khi[key * BSTR + k0 + 2 * t];
                uint32_t bh1 = *(uint32_t*)&Khi[key * BSTR + k0 + 2 * t + 8];
                uint32_t bl0 = *(uint32_t*)&Klo[key * BSTR + k0 + 2 * t];
                uint32_t bl1 = *(uint32_t*)&Klo[key * BSTR + k0 + 2 * t + 8];
                mma_bf16(sacc[fn], ah0, ah1, ah2, ah3, bh0, bh1);
                mma_bf16(sacc[fn], ah0, ah1, ah2, ah3, bl0, bl1);
                mma_bf16(sacc[fn], al0, al1, al2, al3, bh0, bh1);
            }
        }

        // ---- scale + mask ----
        const float scale = 0.125f;
        bool bnd = (s0 + 63 >= q0 + 2048);
#pragma unroll
        for (int fn = 0; fn < 8; fn++) {
#pragma unroll
            for (int e = 0; e < 4; e++) {
                float s = sacc[fn][e] * scale;
                if (bnd) {
                    int col = fn * 8 + 2 * t + (e & 1);
                    int rw  = (e < 2) ? row0 : row0 + 8;
                    if (s0 + col >= q0 + rw + 2048) s = -1e30f;
                }
                sacc[fn][e] = s;
            }
        }

        // ---- row max (warp-local over t: shfl xor 1,2) ----
        float rm0 = -INFINITY, rm1 = -INFINITY;
#pragma unroll
        for (int fn = 0; fn < 8; fn++) {
            rm0 = fmaxf(rm0, fmaxf(sacc[fn][0], sacc[fn][1]));
            rm1 = fmaxf(rm1, fmaxf(sacc[fn][2], sacc[fn][3]));
        }
        rm0 = fmaxf(rm0, __shfl_xor_sync(0xffffffffu, rm0, 1));
        rm0 = fmaxf(rm0, __shfl_xor_sync(0xffffffffu, rm0, 2));
        rm1 = fmaxf(rm1, __shfl_xor_sync(0xffffffffu, rm1, 1));
        rm1 = fmaxf(rm1, __shfl_xor_sync(0xffffffffu, rm1, 2));

        float mn0 = fmaxf(m0, rm0), mn1 = fmaxf(m1, rm1);
        float a0s = __expf(m0 - mn0), a1s = __expf(m1 - mn1);
        m0 = mn0; m1 = mn1;

        // ---- P = exp(S - m) in place, row sums ----
        float rs0 = 0.0f, rs1 = 0.0f;
#pragma unroll
        for (int fn = 0; fn < 8; fn++) {
            float p0 = __expf(sacc[fn][0] - m0);
            float p1 = __expf(sacc[fn][1] - m0);
            float p2 = __expf(sacc[fn][2] - m1);
            float p3 = __expf(sacc[fn][3] - m1);
            sacc[fn][0] = p0; sacc[fn][1] = p1;
            sacc[fn][2] = p2; sacc[fn][3] = p3;
            rs0 += p0 + p1; rs1 += p2 + p3;
        }
        rs0 += __shfl_xor_sync(0xffffffffu, rs0, 1);
        rs0 += __shfl_xor_sync(0xffffffffu, rs0, 2);
        rs1 += __shfl_xor_sync(0xffffffffu, rs1, 1);
        rs1 += __shfl_xor_sync(0xffffffffu, rs1, 2);
        l0 = l0 * a0s + rs0;
        l1 = l1 * a1s + rs1;

#pragma unroll
        for (int fn = 0; fn < 8; fn++) {
            O[fn][0] *= a0s; O[fn][1] *= a0s;
            O[fn][2] *= a1s; O[fn][3] *= a1s;
        }

        // ---- O += P V: A-fragment = accumulator layout (no shfl) ----
#pragma unroll
        for (int ks = 0; ks < 4; ks++) {
            int k0 = ks << 4;
            // hi/lo bf16 split of the 8 P values this lane owns in key-group
            __nv_bfloat16 h00, r00, h01, r01, h02, r02, h03, r03;
            __nv_bfloat16 h10, r10, h11, r11, h12, r12, h13, r13;
            bsplit(sacc[2 * ks][0], h00, r00);     bsplit(sacc[2 * ks][1], h01, r01);
            bsplit(sacc[2 * ks][2], h02, r02);     bsplit(sacc[2 * ks][3], h03, r03);
            bsplit(sacc[2 * ks + 1][0], h10, r10); bsplit(sacc[2 * ks + 1][1], h11, r11);
            bsplit(sacc[2 * ks + 1][2], h12, r12); bsplit(sacc[2 * ks + 1][3], h13, r13);
            uint32_t ph0 = bpack(h00, h01), ph1 = bpack(h02, h03);
            uint32_t ph2 = bpack(h10, h11), ph3 = bpack(h12, h13);
            uint32_t pl0 = bpack(r00, r01), pl1 = bpack(r02, r03);
            uint32_t pl2 = bpack(r10, r11), pl3 = bpack(r12, r13);
#pragma unroll
            for (int fn = 0; fn < 8; fn++) {
                int dd = fn * 8 + g;
                uint32_t vh0 = *(uint32_t*)&Vthi[dd * BSTR + k0 + 2 * t];
                uint32_t vh1 = *(uint32_t*)&Vthi[dd * BSTR + k0 + 2 * t + 8];
                uint32_t vl0 = *(uint32_t*)&Vtlo[dd * BSTR + k0 + 2 * t];
                uint32_t vl1 = *(uint32_t*)&Vtlo[dd * BSTR + k0 + 2 * t + 8];
                mma_bf16(O[fn], ph0, ph1, ph2, ph3, vh0, vh1);
                mma_bf16(O[fn], ph0, ph1, ph2, ph3, vl0, vl1);
                mma_bf16(O[fn], pl0, pl1, pl2, pl3, vh0, vh1);
            }
        }
    }

    // ---- normalize + store ----
    float inv0 = 1.0f / l0, inv1 = 1.0f / l1;
#pragma unroll
    for (int fn = 0; fn < 8; fn++) {
        int col = col0 + fn * 8 + 2 * t;
        *(float2*)&Y[(size_t)(q0 + row0) * D_MOD + col] =
            make_float2(O[fn][0] * inv0, O[fn][1] * inv0);
        *(float2*)&Y[(size_t)(q0 + row0 + 8) * D_MOD + col] =
            make_float2(O[fn][2] * inv1, O[fn][3] * inv1);
    }
}

// ---------------------------------------------------------------------------
extern "C" void kernel_launch(void* const* d_in, const int* in_sizes, int n_in,
                              void* d_out, int out_size)
{
    (void)in_sizes; (void)n_in; (void)out_size;
    const float* l        = (const float*)d_in[0];
    const float* x        = (const float*)d_in[1];
    const float* W_attn_l = (const float*)d_in[2];
    const float* b_attn_l = (const float*)d_in[3];
    const float* W_attn_c = (const float*)d_in[4];
    const float* b_attn_c = (const float*)d_in[5];
    const float* W_q      = (const float*)d_in[6];
    const float* b_q      = (const float*)d_in[7];
    const float* W_proj   = (const float*)d_in[8];
    const float* b_proj   = (const float*)d_in[9];
    float* out = (float*)d_out;

    float *Kp, *Vp, *Qp, *Yp;
    cudaGetSymbolAddress((void**)&Kp, g_K);
    cudaGetSymbolAddress((void**)&Vp, g_V);
    cudaGetSymbolAddress((void**)&Qp, g_Q);
    cudaGetSymbolAddress((void**)&Yp, g_Y);

    dim3 blk(256);

    gemm_tf32_bias_kernel<<<dim3(16, 16), blk>>>(l, W_attn_l, b_attn_l, Kp, Vp, 2048, 0);
    gemm_tf32_bias_kernel<<<dim3(16, 16), blk>>>(x, W_attn_c, b_attn_c, Kp, Vp, 2048, 2048);
    gemm_tf32_bias_kernel<<<dim3(8, 16), blk>>>(x, W_q, b_q, Qp, nullptr, 1024, 0);

    // attention: 16 q-blocks of 128, 16 heads; smem = 73728 B
    size_t smem = (size_t)(2 * 128 + 4 * 64) * BSTR * sizeof(__nv_bfloat16);
    cudaFuncSetAttribute(attn_mma_kernel, cudaFuncAttributeMaxDynamicSharedMemorySize, (int)smem);
    attn_mma_kernel<<<dim3(16, 16), blk, smem>>>(Qp, Kp, Vp, Yp);

    gemm_tf32_bias_kernel<<<dim3(8, 16), blk>>>(Yp, W_proj, b_proj, out, nullptr, 1024, 0);
}

// round 11
// speedup vs baseline: 2.8378x; 1.2015x over previous
#include <cuda_runtime.h>
#include <cuda_bf16.h>
#include <math.h>
#include <stdint.h>

// Problem constants: B=1, T=2048, D=1024, H=16, HD=64
#define T_SEQ 2048
#define D_MOD 1024
#define NH    16
#define HDIM  64

// Scratch (allocation-free rule: __device__ globals)
// Pre-split bf16 operands produced by the projection GEMM epilogues:
__device__ __nv_bfloat16 g_Khi[4096 * 1024];   // K natural [s][1024]
__device__ __nv_bfloat16 g_Klo[4096 * 1024];
__device__ __nv_bfloat16 g_VThi[1024 * 4096];  // V transposed [d][4096]
__device__ __nv_bfloat16 g_VTlo[1024 * 4096];
__device__ __nv_bfloat16 g_Qhi[2048 * 1024];   // Q natural [q][1024]
__device__ __nv_bfloat16 g_Qlo[2048 * 1024];
__device__ float g_Y[T_SEQ * D_MOD];           // attention output (fp32, proj input)

// ---------------------------------------------------------------------------
// helpers
// ---------------------------------------------------------------------------
__device__ __forceinline__ float to_tf32(float f) {
    uint32_t u;
    asm("cvt.rna.tf32.f32 %0, %1;" : "=r"(u) : "f"(f));
    return __uint_as_float(u);
}

__device__ __forceinline__ void mma_tf32(float* c,
    uint32_t a0, uint32_t a1, uint32_t a2, uint32_t a3,
    uint32_t b0, uint32_t b1)
{
    asm volatile(
        "mma.sync.aligned.m16n8k8.row.col.f32.tf32.tf32.f32 "
        "{%0,%1,%2,%3}, {%4,%5,%6,%7}, {%8,%9}, {%0,%1,%2,%3};\n"
        : "+f"(c[0]), "+f"(c[1]), "+f"(c[2]), "+f"(c[3])
        : "r"(a0), "r"(a1), "r"(a2), "r"(a3), "r"(b0), "r"(b1));
}

__device__ __forceinline__ void mma_bf16(float* c,
    uint32_t a0, uint32_t a1, uint32_t a2, uint32_t a3,
    uint32_t b0, uint32_t b1)
{
    asm volatile(
        "mma.sync.aligned.m16n8k16.row.col.f32.bf16.bf16.f32 "
        "{%0,%1,%2,%3}, {%4,%5,%6,%7}, {%8,%9}, {%0,%1,%2,%3};\n"
        : "+f"(c[0]), "+f"(c[1]), "+f"(c[2]), "+f"(c[3])
        : "r"(a0), "r"(a1), "r"(a2), "r"(a3), "r"(b0), "r"(b1));
}

__device__ __forceinline__ void bsplit(float x, __nv_bfloat16& h, __nv_bfloat16& l) {
    h = __float2bfloat16(x);
    l = __float2bfloat16(x - __bfloat162float(h));
}

__device__ __forceinline__ uint32_t bpack(__nv_bfloat16 lo, __nv_bfloat16 hi) {
    __nv_bfloat162 p = __halves2bfloat162(lo, hi);   // lo -> bits[0:16)
    return *(uint32_t*)&p;
}

__device__ __forceinline__ void cp16(uint32_t dst, const void* src) {
    asm volatile("cp.async.cg.shared.global [%0], [%1], 16;\n" :: "r"(dst), "l"(src));
}
#define CP_COMMIT() asm volatile("cp.async.commit_group;\n" ::: "memory")
#define CP_WAIT1()  asm volatile("cp.async.wait_group 1;\n" ::: "memory")

__device__ __forceinline__ uint32_t sma(const void* p) {
    return (uint32_t)__cvta_generic_to_shared(p);
}

// ---------------------------------------------------------------------------
// tf32 tensor-core GEMM with bias.
// Epilogue modes:
//   outf != null  -> plain fp32 store (ld 1024)            [proj]
//   else col<1024 -> bf16 hi/lo natural store to nhi/nlo   [K rows, Q]
//   else          -> bf16 hi/lo TRANSPOSED store thi/tlo   [V -> VT[d][4096]]
// ---------------------------------------------------------------------------
#define AS_STRIDE 36
#define BS_STRIDE 136

__global__ __launch_bounds__(256) void gemm_tf32_bias_kernel(
    const float* __restrict__ A, const float* __restrict__ W,
    const float* __restrict__ bias,
    float* __restrict__ outf,
    __nv_bfloat16* __restrict__ nhi, __nv_bfloat16* __restrict__ nlo,
    __nv_bfloat16* __restrict__ thi, __nv_bfloat16* __restrict__ tlo,
    int N, int rowoff)
{
    __shared__ float As[128 * AS_STRIDE];
    __shared__ float Bs[32 * BS_STRIDE];

    const int tid  = threadIdx.x;
    const int wid  = tid >> 5;
    const int lane = tid & 31;
    const int g    = lane >> 2;
    const int t    = lane & 3;
    const int warp_m = wid >> 2;
    const int warp_n = wid & 3;

    const int m0 = blockIdx.y << 7;
    const int n0 = blockIdx.x << 7;

    int ar[4], ac[4], br[4], bc[4];
#pragma unroll
    for (int i = 0; i < 4; i++) {
        int lin = tid + (i << 8);
        ar[i] = lin >> 3;
        ac[i] = (lin & 7) << 2;
        br[i] = lin >> 5;
        bc[i] = (lin & 31) << 2;
    }

    float acc[4][4][4];
#pragma unroll
    for (int fm = 0; fm < 4; fm++)
#pragma unroll
        for (int fn = 0; fn < 4; fn++)
#pragma unroll
            for (int e = 0; e < 4; e++) acc[fm][fn][e] = 0.0f;

    float4 pa[4], pb[4];
#pragma unroll
    for (int i = 0; i < 4; i++) {
        pa[i] = *(const float4*)&A[(size_t)(m0 + ar[i]) * 1024 + ac[i]];
        pb[i] = *(const float4*)&W[(size_t)br[i] * N + n0 + bc[i]];
    }

    for (int kt = 0; kt < 32; kt++) {
#pragma unroll
        for (int i = 0; i < 4; i++) {
            float* pdst = &As[ar[i] * AS_STRIDE + ac[i]];
            pdst[0] = to_tf32(pa[i].x); pdst[1] = to_tf32(pa[i].y);
            pdst[2] = to_tf32(pa[i].z); pdst[3] = to_tf32(pa[i].w);
            float* qdst = &Bs[br[i] * BS_STRIDE + bc[i]];
            qdst[0] = to_tf32(pb[i].x); qdst[1] = to_tf32(pb[i].y);
            qdst[2] = to_tf32(pb[i].z); qdst[3] = to_tf32(pb[i].w);
        }
        __syncthreads();

        if (kt < 31) {
            int k0 = (kt + 1) << 5;
#pragma unroll
            for (int i = 0; i < 4; i++) {
                pa[i] = *(const float4*)&A[(size_t)(m0 + ar[i]) * 1024 + k0 + ac[i]];
                pb[i] = *(const float4*)&W[(size_t)(k0 + br[i]) * N + n0 + bc[i]];
            }
        }

#pragma unroll
        for (int ks = 0; ks < 4; ks++) {
            int k0 = ks << 3;
            uint32_t b0[4], b1[4];
#pragma unroll
            for (int fn = 0; fn < 4; fn++) {
                int nb = warp_n * 32 + fn * 8 + g;
                b0[fn] = __float_as_uint(Bs[(k0 + t) * BS_STRIDE + nb]);
                b1[fn] = __float_as_uint(Bs[(k0 + t + 4) * BS_STRIDE + nb]);
            }
#pragma unroll
            for (int fm = 0; fm < 4; fm++) {
                int mr = warp_m * 64 + fm * 16 + g;
                uint32_t a0 = __float_as_uint(As[mr * AS_STRIDE + k0 + t]);
                uint32_t a1 = __float_as_uint(As[(mr + 8) * AS_STRIDE + k0 + t]);
                uint32_t a2 = __float_as_uint(As[mr * AS_STRIDE + k0 + 4 + t]);
                uint32_t a3 = __float_as_uint(As[(mr + 8) * AS_STRIDE + k0 + 4 + t]);
#pragma unroll
                for (int fn = 0; fn < 4; fn++)
                    mma_tf32(acc[fm][fn], a0, a1, a2, a3, b0[fn], b1[fn]);
            }
        }
        __syncthreads();
    }

#pragma unroll
    for (int fm = 0; fm < 4; fm++) {
        int row = m0 + warp_m * 64 + fm * 16 + g;
        int srow = rowoff + row;
#pragma unroll
        for (int fn = 0; fn < 4; fn++) {
            int col = n0 + warp_n * 32 + fn * 8 + 2 * t;
            float bx = bias[col], by = bias[col + 1];
            float v0x = acc[fm][fn][0] + bx, v0y = acc[fm][fn][1] + by;
            float v1x = acc[fm][fn][2] + bx, v1y = acc[fm][fn][3] + by;
            if (outf) {
                *(float2*)&outf[(size_t)srow * 1024 + col] = make_float2(v0x, v0y);
                *(float2*)&outf[(size_t)(srow + 8) * 1024 + col] = make_float2(v1x, v1y);
            } else if (col < 1024) {
                __nv_bfloat16 h0, l0, h1, l1, h2, l2, h3, l3;
                bsplit(v0x, h0, l0); bsplit(v0y, h1, l1);
                bsplit(v1x, h2, l2); bsplit(v1y, h3, l3);
                *(uint32_t*)&nhi[(size_t)srow * 1024 + col] = bpack(h0, h1);
                *(uint32_t*)&nlo[(size_t)srow * 1024 + col] = bpack(l0, l1);
                *(uint32_t*)&nhi[(size_t)(srow + 8) * 1024 + col] = bpack(h2, h3);
                *(uint32_t*)&nlo[(size_t)(srow + 8) * 1024 + col] = bpack(l2, l3);
            } else {
                int d0 = col - 1024;
                __nv_bfloat16 h0, l0, h1, l1, h2, l2, h3, l3;
                bsplit(v0x, h0, l0); bsplit(v0y, h1, l1);
                bsplit(v1x, h2, l2); bsplit(v1y, h3, l3);
                thi[(size_t)d0 * 4096 + srow] = h0;       tlo[(size_t)d0 * 4096 + srow] = l0;
                thi[(size_t)(d0 + 1) * 4096 + srow] = h1; tlo[(size_t)(d0 + 1) * 4096 + srow] = l1;
                thi[(size_t)d0 * 4096 + srow + 8] = h2;   tlo[(size_t)d0 * 4096 + srow + 8] = l2;
                thi[(size_t)(d0 + 1) * 4096 + srow + 8] = h3; tlo[(size_t)(d0 + 1) * 4096 + srow + 8] = l3;
            }
        }
    }
}

// ---------------------------------------------------------------------------
// Tensor-core flash attention v4: pre-split bf16 operands, cp.async
// double-buffered K/V tiles (zero loader ALU, zero STS, overlapped loads).
// Block: 128 queries x 1 head, 256 threads = 8 warps; warp owns 16 rows.
// smem: Qhi/Qlo [128][72] + {Kh,Kl,Vh,Vl}[2][64][72] bf16 = 110592 B.
// All hot-loop LDS.32 fragment gathers are bank-conflict-free (4g+t).
// ---------------------------------------------------------------------------
#define BSTR 72   // bf16 row stride (144 B = 36 words; bank = 4*row + t)

__device__ __forceinline__ void load_tile_async(
    int tid, int col0, int s0,
    const __nv_bfloat16* __restrict__ Khi_g, const __nv_bfloat16* __restrict__ Klo_g,
    const __nv_bfloat16* __restrict__ VThi_g, const __nv_bfloat16* __restrict__ VTlo_g,
    __nv_bfloat16* Kh, __nv_bfloat16* Kl, __nv_bfloat16* Vh, __nv_bfloat16* Vl)
{
#pragma unroll
    for (int c = 0; c < 2; c++) {
        int idx = (tid << 1) + c;          // 0..511
        int j = idx >> 3;                  // 0..63
        int ch = (idx & 7) << 3;           // bf16 offset, 16B chunks
        cp16(sma(Kh + j * BSTR + ch), Khi_g + (size_t)(s0 + j) * 1024 + col0 + ch);
        cp16(sma(Kl + j * BSTR + ch), Klo_g + (size_t)(s0 + j) * 1024 + col0 + ch);
        cp16(sma(Vh + j * BSTR + ch), VThi_g + (size_t)(col0 + j) * 4096 + s0 + ch);
        cp16(sma(Vl + j * BSTR + ch), VTlo_g + (size_t)(col0 + j) * 4096 + s0 + ch);
    }
}

__global__ __launch_bounds__(256, 2) void attn_mma_kernel(
    const __nv_bfloat16* __restrict__ Qhi_g, const __nv_bfloat16* __restrict__ Qlo_g,
    const __nv_bfloat16* __restrict__ Khi_g, const __nv_bfloat16* __restrict__ Klo_g,
    const __nv_bfloat16* __restrict__ VThi_g, const __nv_bfloat16* __restrict__ VTlo_g,
    float* __restrict__ Y)
{
    extern __shared__ char smraw[];
    __nv_bfloat16* Qhi_s = (__nv_bfloat16*)smraw;     // [128][BSTR]
    __nv_bfloat16* Qlo_s = Qhi_s + 128 * BSTR;
    __nv_bfloat16* Kh_s  = Qlo_s + 128 * BSTR;        // [2][64][BSTR]
    __nv_bfloat16* Kl_s  = Kh_s + 2 * 64 * BSTR;
    __nv_bfloat16* Vh_s  = Kl_s + 2 * 64 * BSTR;
    __nv_bfloat16* Vl_s  = Vh_s + 2 * 64 * BSTR;

    const int tid  = threadIdx.x;
    const int wid  = tid >> 5;
    const int lane = tid & 31;
    const int g    = lane >> 2;   // 0..7
    const int t    = lane & 3;    // 0..3

    const int h  = blockIdx.y;
    const int q0 = blockIdx.x << 7;
    const int col0 = h * HDIM;

    const int row0 = wid * 16 + g;
    const int ntiles = (q0 >> 6) + 34;   // >= 34

    // ---- prologue: async-load Q (whole tile) + tile0 into buf0 (group 0) ----
#pragma unroll
    for (int c = 0; c < 4; c++) {
        int idx = (tid << 2) + c;          // 0..1023
        int r = idx >> 3;
        int ch = (idx & 7) << 3;
        cp16(sma(Qhi_s + r * BSTR + ch), Qhi_g + (size_t)(q0 + r) * 1024 + col0 + ch);
        cp16(sma(Qlo_s + r * BSTR + ch), Qlo_g + (size_t)(q0 + r) * 1024 + col0 + ch);
    }
    load_tile_async(tid, col0, 0, Khi_g, Klo_g, VThi_g, VTlo_g, Kh_s, Kl_s, Vh_s, Vl_s);
    CP_COMMIT();
    // tile1 into buf1 (group 1); ntiles >= 34 so tile1 always exists
    load_tile_async(tid, col0, 64, Khi_g, Klo_g, VThi_g, VTlo_g,
                    Kh_s + 64 * BSTR, Kl_s + 64 * BSTR, Vh_s + 64 * BSTR, Vl_s + 64 * BSTR);
    CP_COMMIT();

    float O[8][4];
#pragma unroll
    for (int fn = 0; fn < 8; fn++)
#pragma unroll
        for (int e = 0; e < 4; e++) O[fn][e] = 0.0f;
    float m0 = -INFINITY, m1 = -INFINITY, l0 = 0.0f, l1 = 0.0f;

    for (int tt = 0; tt < ntiles; tt++) {
        int s0 = tt << 6;
        int p = tt & 1;
        const __nv_bfloat16* Kh = Kh_s + p * 64 * BSTR;
        const __nv_bfloat16* Kl = Kl_s + p * 64 * BSTR;
        const __nv_bfloat16* Vh = Vh_s + p * 64 * BSTR;
        const __nv_bfloat16* Vl = Vl_s + p * 64 * BSTR;

        CP_WAIT1();          // tile tt (and Q for tt=0) landed
        __syncthreads();

        // ---- S = Q K^T via 3-mma bf16 split (lo*lo dropped) ----
        float sacc[8][4];
#pragma unroll
        for (int fn = 0; fn < 8; fn++)
#pragma unroll
            for (int e = 0; e < 4; e++) sacc[fn][e] = 0.0f;

#pragma unroll
        for (int ks = 0; ks < 4; ks++) {
            int k0 = ks << 4;
            uint32_t ah0 = *(uint32_t*)&Qhi_s[row0 * BSTR + k0 + 2 * t];
            uint32_t ah1 = *(uint32_t*)&Qhi_s[(row0 + 8) * BSTR + k0 + 2 * t];
            uint32_t ah2 = *(uint32_t*)&Qhi_s[row0 * BSTR + k0 + 2 * t + 8];
            uint32_t ah3 = *(uint32_t*)&Qhi_s[(row0 + 8) * BSTR + k0 + 2 * t + 8];
            uint32_t al0 = *(uint32_t*)&Qlo_s[row0 * BSTR + k0 + 2 * t];
            uint32_t al1 = *(uint32_t*)&Qlo_s[(row0 + 8) * BSTR + k0 + 2 * t];
            uint32_t al2 = *(uint32_t*)&Qlo_s[row0 * BSTR + k0 + 2 * t + 8];
            uint32_t al3 = *(uint32_t*)&Qlo_s[(row0 + 8) * BSTR + k0 + 2 * t + 8];
#pragma unroll
            for (int fn = 0; fn < 8; fn++) {
                int key = fn * 8 + g;
                uint32_t bh0 = *(uint32_t*)&Kh[key * BSTR + k0 + 2 * t];
                uint32_t bh1 = *(uint32_t*)&Kh[key * BSTR + k0 + 2 * t + 8];
                uint32_t bl0 = *(uint32_t*)&Kl[key * BSTR + k0 + 2 * t];
                uint32_t bl1 = *(uint32_t*)&Kl[key * BSTR + k0 + 2 * t + 8];
                mma_bf16(sacc[fn], ah0, ah1, ah2, ah3, bh0, bh1);
                mma_bf16(sacc[fn], ah0, ah1, ah2, ah3, bl0, bl1);
                mma_bf16(sacc[fn], al0, al1, al2, al3, bh0, bh1);
            }
        }

        // ---- scale + mask ----
        const float scale = 0.125f;
        bool bnd = (s0 + 63 >= q0 + 2048);
#pragma unroll
        for (int fn = 0; fn < 8; fn++) {
#pragma unroll
            for (int e = 0; e < 4; e++) {
                float s = sacc[fn][e] * scale;
                if (bnd) {
                    int col = fn * 8 + 2 * t + (e & 1);
                    int rw  = (e < 2) ? row0 : row0 + 8;
                    if (s0 + col >= q0 + rw + 2048) s = -1e30f;
                }
                sacc[fn][e] = s;
            }
        }

        // ---- row max (warp-local over t: shfl xor 1,2) ----
        float rm0 = -INFINITY, rm1 = -INFINITY;
#pragma unroll
        for (int fn = 0; fn < 8; fn++) {
            rm0 = fmaxf(rm0, fmaxf(sacc[fn][0], sacc[fn][1]));
            rm1 = fmaxf(rm1, fmaxf(sacc[fn][2], sacc[fn][3]));
        }
        rm0 = fmaxf(rm0, __shfl_xor_sync(0xffffffffu, rm0, 1));
        rm0 = fmaxf(rm0, __shfl_xor_sync(0xffffffffu, rm0, 2));
        rm1 = fmaxf(rm1, __shfl_xor_sync(0xffffffffu, rm1, 1));
        rm1 = fmaxf(rm1, __shfl_xor_sync(0xffffffffu, rm1, 2));

        float mn0 = fmaxf(m0, rm0), mn1 = fmaxf(m1, rm1);
        float a0s = __expf(m0 - mn0), a1s = __expf(m1 - mn1);
        m0 = mn0; m1 = mn1;

        // ---- P = exp(S - m) in place, row sums ----
        float rs0 = 0.0f, rs1 = 0.0f;
#pragma unroll
        for (int fn = 0; fn < 8; fn++) {
            float p0 = __expf(sacc[fn][0] - m0);
            float p1 = __expf(sacc[fn][1] - m0);
            float p2 = __expf(sacc[fn][2] - m1);
            float p3 = __expf(sacc[fn][3] - m1);
            sacc[fn][0] = p0; sacc[fn][1] = p1;
            sacc[fn][2] = p2; sacc[fn][3] = p3;
            rs0 += p0 + p1; rs1 += p2 + p3;
        }
        rs0 += __shfl_xor_sync(0xffffffffu, rs0, 1);
        rs0 += __shfl_xor_sync(0xffffffffu, rs0, 2);
        rs1 += __shfl_xor_sync(0xffffffffu, rs1, 1);
        rs1 += __shfl_xor_sync(0xffffffffu, rs1, 2);
        l0 = l0 * a0s + rs0;
        l1 = l1 * a1s + rs1;

#pragma unroll
        for (int fn = 0; fn < 8; fn++) {
            O[fn][0] *= a0s; O[fn][1] *= a0s;
            O[fn][2] *= a1s; O[fn][3] *= a1s;
        }

        // ---- O += P V: A-fragment = accumulator layout (no shfl) ----
#pragma unroll
        for (int ks = 0; ks < 4; ks++) {
            int k0 = ks << 4;
            __nv_bfloat16 h00, r00, h01, r01, h02, r02, h03, r03;
            __nv_bfloat16 h10, r10, h11, r11, h12, r12, h13, r13;
            bsplit(sacc[2 * ks][0], h00, r00);     bsplit(sacc[2 * ks][1], h01, r01);
            bsplit(sacc[2 * ks][2], h02, r02);     bsplit(sacc[2 * ks][3], h03, r03);
            bsplit(sacc[2 * ks + 1][0], h10, r10); bsplit(sacc[2 * ks + 1][1], h11, r11);
            bsplit(sacc[2 * ks + 1][2], h12, r12); bsplit(sacc[2 * ks + 1][3], h13, r13);
            uint32_t ph0 = bpack(h00, h01), ph1 = bpack(h02, h03);
            uint32_t ph2 = bpack(h10, h11), ph3 = bpack(h12, h13);
            uint32_t pl0 = bpack(r00, r01), pl1 = bpack(r02, r03);
            uint32_t pl2 = bpack(r10, r11), pl3 = bpack(r12, r13);
#pragma unroll
            for (int fn = 0; fn < 8; fn++) {
                int dd = fn * 8 + g;
                uint32_t vh0 = *(uint32_t*)&Vh[dd * BSTR + k0 + 2 * t];
                uint32_t vh1 = *(uint32_t*)&Vh[dd * BSTR + k0 + 2 * t + 8];
                uint32_t vl0 = *(uint32_t*)&Vl[dd * BSTR + k0 + 2 * t];
                uint32_t vl1 = *(uint32_t*)&Vl[dd * BSTR + k0 + 2 * t + 8];
                mma_bf16(O[fn], ph0, ph1, ph2, ph3, vh0, vh1);
                mma_bf16(O[fn], ph0, ph1, ph2, ph3, vl0, vl1);
                mma_bf16(O[fn], pl0, pl1, pl2, pl3, vh0, vh1);
            }
        }

        __syncthreads();   // all warps done reading buffer p
        int nt = tt + 2;
        if (nt < ntiles) {
            load_tile_async(tid, col0, nt << 6, Khi_g, Klo_g, VThi_g, VTlo_g,
                            Kh_s + p * 64 * BSTR, Kl_s + p * 64 * BSTR,
                            Vh_s + p * 64 * BSTR, Vl_s + p * 64 * BSTR);
        }
        CP_COMMIT();   // keep group numbering aligned even when empty
    }

    // ---- normalize + store ----
    float inv0 = 1.0f / l0, inv1 = 1.0f / l1;
#pragma unroll
    for (int fn = 0; fn < 8; fn++) {
        int col = col0 + fn * 8 + 2 * t;
        *(float2*)&Y[(size_t)(q0 + row0) * D_MOD + col] =
            make_float2(O[fn][0] * inv0, O[fn][1] * inv0);
        *(float2*)&Y[(size_t)(q0 + row0 + 8) * D_MOD + col] =
            make_float2(O[fn][2] * inv1, O[fn][3] * inv1);
    }
}

// ---------------------------------------------------------------------------
extern "C" void kernel_launch(void* const* d_in, const int* in_sizes, int n_in,
                              void* d_out, int out_size)
{
    (void)in_sizes; (void)n_in; (void)out_size;
    const float* l        = (const float*)d_in[0];
    const float* x        = (const float*)d_in[1];
    const float* W_attn_l = (const float*)d_in[2];
    const float* b_attn_l = (const float*)d_in[3];
    const float* W_attn_c = (const float*)d_in[4];
    const float* b_attn_c = (const float*)d_in[5];
    const float* W_q      = (const float*)d_in[6];
    const float* b_q      = (const float*)d_in[7];
    const float* W_proj   = (const float*)d_in[8];
    const float* b_proj   = (const float*)d_in[9];
    float* out = (float*)d_out;

    __nv_bfloat16 *Khi, *Klo, *VThi, *VTlo, *Qhi, *Qlo;
    float* Yp;
    cudaGetSymbolAddress((void**)&Khi, g_Khi);
    cudaGetSymbolAddress((void**)&Klo, g_Klo);
    cudaGetSymbolAddress((void**)&VThi, g_VThi);
    cudaGetSymbolAddress((void**)&VTlo, g_VTlo);
    cudaGetSymbolAddress((void**)&Qhi, g_Qhi);
    cudaGetSymbolAddress((void**)&Qlo, g_Qlo);
    cudaGetSymbolAddress((void**)&Yp, g_Y);

    dim3 blk(256);

    // kv_l -> K/VT rows 0:2048 ; kv_c -> rows 2048:4096 (bf16 hi/lo direct)
    gemm_tf32_bias_kernel<<<dim3(16, 16), blk>>>(l, W_attn_l, b_attn_l,
        nullptr, Khi, Klo, VThi, VTlo, 2048, 0);
    gemm_tf32_bias_kernel<<<dim3(16, 16), blk>>>(x, W_attn_c, b_attn_c,
        nullptr, Khi, Klo, VThi, VTlo, 2048, 2048);
    // q -> bf16 hi/lo natural
    gemm_tf32_bias_kernel<<<dim3(8, 16), blk>>>(x, W_q, b_q,
        nullptr, Qhi, Qlo, nullptr, nullptr, 1024, 0);

    // attention: 16 q-blocks of 128, 16 heads; smem = 110592 B (2 CTA/SM)
    size_t smem = (size_t)(2 * 128 + 8 * 64) * BSTR * sizeof(__nv_bfloat16);
    cudaFuncSetAttribute(attn_mma_kernel, cudaFuncAttributeMaxDynamicSharedMemorySize, (int)smem);
    attn_mma_kernel<<<dim3(16, 16), blk, smem>>>(Qhi, Qlo, Khi, Klo, VThi, VTlo, Yp);

    // output projection (fp32 path)
    gemm_tf32_bias_kernel<<<dim3(8, 16), blk>>>(Yp, W_proj, b_proj,
        out, nullptr, nullptr, nullptr, nullptr, 1024, 0);
}

// round 12
// speedup vs baseline: 3.1132x; 1.0971x over previous
#include <cuda_runtime.h>
#include <cuda_bf16.h>
#include <math.h>
#include <stdint.h>

// Problem constants: B=1, T=2048, D=1024, H=16, HD=64
#define T_SEQ 2048
#define D_MOD 1024
#define NH    16
#define HDIM  64

// Scratch (allocation-free rule: __device__ globals)
__device__ __nv_bfloat16 g_Khi[4096 * 1024];   // K natural [s][1024]
__device__ __nv_bfloat16 g_Klo[4096 * 1024];
__device__ __nv_bfloat16 g_VThi[1024 * 4096];  // V transposed [d][4096]
__device__ __nv_bfloat16 g_VTlo[1024 * 4096];
__device__ __nv_bfloat16 g_Qhi[2048 * 1024];   // Q natural [q][1024]
__device__ __nv_bfloat16 g_Qlo[2048 * 1024];
__device__ float g_Y[T_SEQ * D_MOD];           // attention output (fp32, proj input)
// split-KV partials
__device__ float g_Op[2][NH][16][128][64];     // unnormalized partial O (16.8 MB)
__device__ float g_ml[2][NH][16][2][128];      // [0]=m, [1]=l per row

// ---------------------------------------------------------------------------
// helpers
// ---------------------------------------------------------------------------
__device__ __forceinline__ float to_tf32(float f) {
    uint32_t u;
    asm("cvt.rna.tf32.f32 %0, %1;" : "=r"(u) : "f"(f));
    return __uint_as_float(u);
}

__device__ __forceinline__ void mma_tf32(float* c,
    uint32_t a0, uint32_t a1, uint32_t a2, uint32_t a3,
    uint32_t b0, uint32_t b1)
{
    asm volatile(
        "mma.sync.aligned.m16n8k8.row.col.f32.tf32.tf32.f32 "
        "{%0,%1,%2,%3}, {%4,%5,%6,%7}, {%8,%9}, {%0,%1,%2,%3};\n"
        : "+f"(c[0]), "+f"(c[1]), "+f"(c[2]), "+f"(c[3])
        : "r"(a0), "r"(a1), "r"(a2), "r"(a3), "r"(b0), "r"(b1));
}

__device__ __forceinline__ void mma_bf16(float* c,
    uint32_t a0, uint32_t a1, uint32_t a2, uint32_t a3,
    uint32_t b0, uint32_t b1)
{
    asm volatile(
        "mma.sync.aligned.m16n8k16.row.col.f32.bf16.bf16.f32 "
        "{%0,%1,%2,%3}, {%4,%5,%6,%7}, {%8,%9}, {%0,%1,%2,%3};\n"
        : "+f"(c[0]), "+f"(c[1]), "+f"(c[2]), "+f"(c[3])
        : "r"(a0), "r"(a1), "r"(a2), "r"(a3), "r"(b0), "r"(b1));
}

__device__ __forceinline__ void bsplit(float x, __nv_bfloat16& h, __nv_bfloat16& l) {
    h = __float2bfloat16(x);
    l = __float2bfloat16(x - __bfloat162float(h));
}

__device__ __forceinline__ uint32_t bpack(__nv_bfloat16 lo, __nv_bfloat16 hi) {
    __nv_bfloat162 p = __halves2bfloat162(lo, hi);   // lo -> bits[0:16)
    return *(uint32_t*)&p;
}

__device__ __forceinline__ void cp16(uint32_t dst, const void* src) {
    asm volatile("cp.async.cg.shared.global [%0], [%1], 16;\n" :: "r"(dst), "l"(src));
}
#define CP_COMMIT() asm volatile("cp.async.commit_group;\n" ::: "memory")
#define CP_WAIT1()  asm volatile("cp.async.wait_group 1;\n" ::: "memory")

__device__ __forceinline__ uint32_t sma(const void* p) {
    return (uint32_t)__cvta_generic_to_shared(p);
}

// ---------------------------------------------------------------------------
// tf32 tensor-core GEMM with bias (unchanged from measured R11 kernel)
// ---------------------------------------------------------------------------
#define AS_STRIDE 36
#define BS_STRIDE 136

__global__ __launch_bounds__(256) void gemm_tf32_bias_kernel(
    const float* __restrict__ A, const float* __restrict__ W,
    const float* __restrict__ bias,
    float* __restrict__ outf,
    __nv_bfloat16* __restrict__ nhi, __nv_bfloat16* __restrict__ nlo,
    __nv_bfloat16* __restrict__ thi, __nv_bfloat16* __restrict__ tlo,
    int N, int rowoff)
{
    __shared__ float As[128 * AS_STRIDE];
    __shared__ float Bs[32 * BS_STRIDE];

    const int tid  = threadIdx.x;
    const int wid  = tid >> 5;
    const int lane = tid & 31;
    const int g    = lane >> 2;
    const int t    = lane & 3;
    const int warp_m = wid >> 2;
    const int warp_n = wid & 3;

    const int m0 = blockIdx.y << 7;
    const int n0 = blockIdx.x << 7;

    int ar[4], ac[4], br[4], bc[4];
#pragma unroll
    for (int i = 0; i < 4; i++) {
        int lin = tid + (i << 8);
        ar[i] = lin >> 3;
        ac[i] = (lin & 7) << 2;
        br[i] = lin >> 5;
        bc[i] = (lin & 31) << 2;
    }

    float acc[4][4][4];
#pragma unroll
    for (int fm = 0; fm < 4; fm++)
#pragma unroll
        for (int fn = 0; fn < 4; fn++)
#pragma unroll
            for (int e = 0; e < 4; e++) acc[fm][fn][e] = 0.0f;

    float4 pa[4], pb[4];
#pragma unroll
    for (int i = 0; i < 4; i++) {
        pa[i] = *(const float4*)&A[(size_t)(m0 + ar[i]) * 1024 + ac[i]];
        pb[i] = *(const float4*)&W[(size_t)br[i] * N + n0 + bc[i]];
    }

    for (int kt = 0; kt < 32; kt++) {
#pragma unroll
        for (int i = 0; i < 4; i++) {
            float* pdst = &As[ar[i] * AS_STRIDE + ac[i]];
            pdst[0] = to_tf32(pa[i].x); pdst[1] = to_tf32(pa[i].y);
            pdst[2] = to_tf32(pa[i].z); pdst[3] = to_tf32(pa[i].w);
            float* qdst = &Bs[br[i] * BS_STRIDE + bc[i]];
            qdst[0] = to_tf32(pb[i].x); qdst[1] = to_tf32(pb[i].y);
            qdst[2] = to_tf32(pb[i].z); qdst[3] = to_tf32(pb[i].w);
        }
        __syncthreads();

        if (kt < 31) {
            int k0 = (kt + 1) << 5;
#pragma unroll
            for (int i = 0; i < 4; i++) {
                pa[i] = *(const float4*)&A[(size_t)(m0 + ar[i]) * 1024 + k0 + ac[i]];
                pb[i] = *(const float4*)&W[(size_t)(k0 + br[i]) * N + n0 + bc[i]];
            }
        }

#pragma unroll
        for (int ks = 0; ks < 4; ks++) {
            int k0 = ks << 3;
            uint32_t b0[4], b1[4];
#pragma unroll
            for (int fn = 0; fn < 4; fn++) {
                int nb = warp_n * 32 + fn * 8 + g;
                b0[fn] = __float_as_uint(Bs[(k0 + t) * BS_STRIDE + nb]);
                b1[fn] = __float_as_uint(Bs[(k0 + t + 4) * BS_STRIDE + nb]);
            }
#pragma unroll
            for (int fm = 0; fm < 4; fm++) {
                int mr = warp_m * 64 + fm * 16 + g;
                uint32_t a0 = __float_as_uint(As[mr * AS_STRIDE + k0 + t]);
                uint32_t a1 = __float_as_uint(As[(mr + 8) * AS_STRIDE + k0 + t]);
                uint32_t a2 = __float_as_uint(As[mr * AS_STRIDE + k0 + 4 + t]);
                uint32_t a3 = __float_as_uint(As[(mr + 8) * AS_STRIDE + k0 + 4 + t]);
#pragma unroll
                for (int fn = 0; fn < 4; fn++)
                    mma_tf32(acc[fm][fn], a0, a1, a2, a3, b0[fn], b1[fn]);
            }
        }
        __syncthreads();
    }

#pragma unroll
    for (int fm = 0; fm < 4; fm++) {
        int row = m0 + warp_m * 64 + fm * 16 + g;
        int srow = rowoff + row;
#pragma unroll
        for (int fn = 0; fn < 4; fn++) {
            int col = n0 + warp_n * 32 + fn * 8 + 2 * t;
            float bx = bias[col], by = bias[col + 1];
            float v0x = acc[fm][fn][0] + bx, v0y = acc[fm][fn][1] + by;
            float v1x = acc[fm][fn][2] + bx, v1y = acc[fm][fn][3] + by;
            if (outf) {
                *(float2*)&outf[(size_t)srow * 1024 + col] = make_float2(v0x, v0y);
                *(float2*)&outf[(size_t)(srow + 8) * 1024 + col] = make_float2(v1x, v1y);
            } else if (col < 1024) {
                __nv_bfloat16 h0, l0, h1, l1, h2, l2, h3, l3;
                bsplit(v0x, h0, l0); bsplit(v0y, h1, l1);
                bsplit(v1x, h2, l2); bsplit(v1y, h3, l3);
                *(uint32_t*)&nhi[(size_t)srow * 1024 + col] = bpack(h0, h1);
                *(uint32_t*)&nlo[(size_t)srow * 1024 + col] = bpack(l0, l1);
                *(uint32_t*)&nhi[(size_t)(srow + 8) * 1024 + col] = bpack(h2, h3);
                *(uint32_t*)&nlo[(size_t)(srow + 8) * 1024 + col] = bpack(l2, l3);
            } else {
                int d0 = col - 1024;
                __nv_bfloat16 h0, l0, h1, l1, h2, l2, h3, l3;
                bsplit(v0x, h0, l0); bsplit(v0y, h1, l1);
                bsplit(v1x, h2, l2); bsplit(v1y, h3, l3);
                thi[(size_t)d0 * 4096 + srow] = h0;       tlo[(size_t)d0 * 4096 + srow] = l0;
                thi[(size_t)(d0 + 1) * 4096 + srow] = h1; tlo[(size_t)(d0 + 1) * 4096 + srow] = l1;
                thi[(size_t)d0 * 4096 + srow + 8] = h2;   tlo[(size_t)d0 * 4096 + srow + 8] = l2;
                thi[(size_t)(d0 + 1) * 4096 + srow + 8] = h3; tlo[(size_t)(d0 + 1) * 4096 + srow + 8] = l3;
            }
        }
    }
}

// ---------------------------------------------------------------------------
// Tensor-core flash attention v5: split-KV for load balance.
// grid = (32, 16): x encodes (qb descending, key-split half), y = head.
// Each CTA computes a partial (unnormalized O, m, l) over its key range;
// attn_combine_kernel merges the two halves. Hot loop identical to v4.
// ---------------------------------------------------------------------------
#define BSTR 72   // bf16 row stride (144 B = 36 words; bank = 4*row + t)

__device__ __forceinline__ void load_tile_async(
    int tid, int col0, int s0,
    const __nv_bfloat16* __restrict__ Khi_g, const __nv_bfloat16* __restrict__ Klo_g,
    const __nv_bfloat16* __restrict__ VThi_g, const __nv_bfloat16* __restrict__ VTlo_g,
    __nv_bfloat16* Kh, __nv_bfloat16* Kl, __nv_bfloat16* Vh, __nv_bfloat16* Vl)
{
#pragma unroll
    for (int c = 0; c < 2; c++) {
        int idx = (tid << 1) + c;          // 0..511
        int j = idx >> 3;                  // 0..63
        int ch = (idx & 7) << 3;           // bf16 offset, 16B chunks
        cp16(sma(Kh + j * BSTR + ch), Khi_g + (size_t)(s0 + j) * 1024 + col0 + ch);
        cp16(sma(Kl + j * BSTR + ch), Klo_g + (size_t)(s0 + j) * 1024 + col0 + ch);
        cp16(sma(Vh + j * BSTR + ch), VThi_g + (size_t)(col0 + j) * 4096 + s0 + ch);
        cp16(sma(Vl + j * BSTR + ch), VTlo_g + (size_t)(col0 + j) * 4096 + s0 + ch);
    }
}

__global__ __launch_bounds__(256, 2) void attn_mma_kernel(
    const __nv_bfloat16* __restrict__ Qhi_g, const __nv_bfloat16* __restrict__ Qlo_g,
    const __nv_bfloat16* __restrict__ Khi_g, const __nv_bfloat16* __restrict__ Klo_g,
    const __nv_bfloat16* __restrict__ VThi_g, const __nv_bfloat16* __restrict__ VTlo_g)
{
    extern __shared__ char smraw[];
    __nv_bfloat16* Qhi_s = (__nv_bfloat16*)smraw;     // [128][BSTR]
    __nv_bfloat16* Qlo_s = Qhi_s + 128 * BSTR;
    __nv_bfloat16* Kh_s  = Qlo_s + 128 * BSTR;        // [2][64][BSTR]
    __nv_bfloat16* Kl_s  = Kh_s + 2 * 64 * BSTR;
    __nv_bfloat16* Vh_s  = Kl_s + 2 * 64 * BSTR;
    __nv_bfloat16* Vl_s  = Vh_s + 2 * 64 * BSTR;

    const int tid  = threadIdx.x;
    const int wid  = tid >> 5;
    const int lane = tid & 31;
    const int g    = lane >> 2;   // 0..7
    const int t    = lane & 3;    // 0..3

    const int bx = blockIdx.x;               // 0..31, largest work first
    const int qb = 15 - (bx >> 1);
    const int split = bx & 1;
    const int h  = blockIdx.y;
    const int q0 = qb << 7;
    const int col0 = h * HDIM;

    const int nt_total = 2 * qb + 34;        // 34..64
    const int nt0 = nt_total >> 1;           // 17..32 (split0: all-latent, unmasked)
    const int tb = split ? nt0 : 0;
    const int te = split ? nt_total : nt0;   // te - tb >= 17

    const int row0 = wid * 16 + g;

    // ---- prologue: async-load Q + tiles tb, tb+1 ----
#pragma unroll
    for (int c = 0; c < 4; c++) {
        int idx = (tid << 2) + c;          // 0..1023
        int r = idx >> 3;
        int ch = (idx & 7) << 3;
        cp16(sma(Qhi_s + r * BSTR + ch), Qhi_g + (size_t)(q0 + r) * 1024 + col0 + ch);
        cp16(sma(Qlo_s + r * BSTR + ch), Qlo_g + (size_t)(q0 + r) * 1024 + col0 + ch);
    }
    load_tile_async(tid, col0, tb << 6, Khi_g, Klo_g, VThi_g, VTlo_g,
                    Kh_s, Kl_s, Vh_s, Vl_s);
    CP_COMMIT();
    load_tile_async(tid, col0, (tb + 1) << 6, Khi_g, Klo_g, VThi_g, VTlo_g,
                    Kh_s + 64 * BSTR, Kl_s + 64 * BSTR, Vh_s + 64 * BSTR, Vl_s + 64 * BSTR);
    CP_COMMIT();

    float O[8][4];
#pragma unroll
    for (int fn = 0; fn < 8; fn++)
#pragma unroll
        for (int e = 0; e < 4; e++) O[fn][e] = 0.0f;
    float m0 = -INFINITY, m1 = -INFINITY, l0 = 0.0f, l1 = 0.0f;

    for (int tt = tb; tt < te; tt++) {
        int s0 = tt << 6;
        int p = (tt - tb) & 1;
        const __nv_bfloat16* Kh = Kh_s + p * 64 * BSTR;
        const __nv_bfloat16* Kl = Kl_s + p * 64 * BSTR;
        const __nv_bfloat16* Vh = Vh_s + p * 64 * BSTR;
        const __nv_bfloat16* Vl = Vl_s + p * 64 * BSTR;

        CP_WAIT1();
        __syncthreads();

        // ---- S = Q K^T via 3-mma bf16 split (lo*lo dropped) ----
        float sacc[8][4];
#pragma unroll
        for (int fn = 0; fn < 8; fn++)
#pragma unroll
            for (int e = 0; e < 4; e++) sacc[fn][e] = 0.0f;

#pragma unroll
        for (int ks = 0; ks < 4; ks++) {
            int k0 = ks << 4;
            uint32_t ah0 = *(uint32_t*)&Qhi_s[row0 * BSTR + k0 + 2 * t];
            uint32_t ah1 = *(uint32_t*)&Qhi_s[(row0 + 8) * BSTR + k0 + 2 * t];
            uint32_t ah2 = *(uint32_t*)&Qhi_s[row0 * BSTR + k0 + 2 * t + 8];
            uint32_t ah3 = *(uint32_t*)&Qhi_s[(row0 + 8) * BSTR + k0 + 2 * t + 8];
            uint32_t al0 = *(uint32_t*)&Qlo_s[row0 * BSTR + k0 + 2 * t];
            uint32_t al1 = *(uint32_t*)&Qlo_s[(row0 + 8) * BSTR + k0 + 2 * t];
            uint32_t al2 = *(uint32_t*)&Qlo_s[row0 * BSTR + k0 + 2 * t + 8];
            uint32_t al3 = *(uint32_t*)&Qlo_s[(row0 + 8) * BSTR + k0 + 2 * t + 8];
#pragma unroll
            for (int fn = 0; fn < 8; fn++) {
                int key = fn * 8 + g;
                uint32_t bh0 = *(uint32_t*)&Kh[key * BSTR + k0 + 2 * t];
                uint32_t bh1 = *(uint32_t*)&Kh[key * BSTR + k0 + 2 * t + 8];
                uint32_t bl0 = *(uint32_t*)&Kl[key * BSTR + k0 + 2 * t];
                uint32_t bl1 = *(uint32_t*)&Kl[key * BSTR + k0 + 2 * t + 8];
                mma_bf16(sacc[fn], ah0, ah1, ah2, ah3, bh0, bh1);
                mma_bf16(sacc[fn], ah0, ah1, ah2, ah3, bl0, bl1);
                mma_bf16(sacc[fn], al0, al1, al2, al3, bh0, bh1);
            }
        }

        // ---- scale + mask ----
        const float scale = 0.125f;
        bool bnd = (s0 + 63 >= q0 + 2048);
#pragma unroll
        for (int fn = 0; fn < 8; fn++) {
#pragma unroll
            for (int e = 0; e < 4; e++) {
                float s = sacc[fn][e] * scale;
                if (bnd) {
                    int col = fn * 8 + 2 * t + (e & 1);
                    int rw  = (e < 2) ? row0 : row0 + 8;
                    if (s0 + col >= q0 + rw + 2048) s = -1e30f;
                }
                sacc[fn][e] = s;
            }
        }

        // ---- row max (warp-local over t: shfl xor 1,2) ----
        float rm0 = -INFINITY, rm1 = -INFINITY;
#pragma unroll
        for (int fn = 0; fn < 8; fn++) {
            rm0 = fmaxf(rm0, fmaxf(sacc[fn][0], sacc[fn][1]));
            rm1 = fmaxf(rm1, fmaxf(sacc[fn][2], sacc[fn][3]));
        }
        rm0 = fmaxf(rm0, __shfl_xor_sync(0xffffffffu, rm0, 1));
        rm0 = fmaxf(rm0, __shfl_xor_sync(0xffffffffu, rm0, 2));
        rm1 = fmaxf(rm1, __shfl_xor_sync(0xffffffffu, rm1, 1));
        rm1 = fmaxf(rm1, __shfl_xor_sync(0xffffffffu, rm1, 2));

        float mn0 = fmaxf(m0, rm0), mn1 = fmaxf(m1, rm1);
        float a0s = __expf(m0 - mn0), a1s = __expf(m1 - mn1);
        m0 = mn0; m1 = mn1;

        // ---- P = exp(S - m) in place, row sums ----
        float rs0 = 0.0f, rs1 = 0.0f;
#pragma unroll
        for (int fn = 0; fn < 8; fn++) {
            float p0 = __expf(sacc[fn][0] - m0);
            float p1 = __expf(sacc[fn][1] - m0);
            float p2 = __expf(sacc[fn][2] - m1);
            float p3 = __expf(sacc[fn][3] - m1);
            sacc[fn][0] = p0; sacc[fn][1] = p1;
            sacc[fn][2] = p2; sacc[fn][3] = p3;
            rs0 += p0 + p1; rs1 += p2 + p3;
        }
        rs0 += __shfl_xor_sync(0xffffffffu, rs0, 1);
        rs0 += __shfl_xor_sync(0xffffffffu, rs0, 2);
        rs1 += __shfl_xor_sync(0xffffffffu, rs1, 1);
        rs1 += __shfl_xor_sync(0xffffffffu, rs1, 2);
        l0 = l0 * a0s + rs0;
        l1 = l1 * a1s + rs1;

#pragma unroll
        for (int fn = 0; fn < 8; fn++) {
            O[fn][0] *= a0s; O[fn][1] *= a0s;
            O[fn][2] *= a1s; O[fn][3] *= a1s;
        }

        // ---- O += P V: A-fragment = accumulator layout (no shfl) ----
#pragma unroll
        for (int ks = 0; ks < 4; ks++) {
            int k0 = ks << 4;
            __nv_bfloat16 h00, r00, h01, r01, h02, r02, h03, r03;
            __nv_bfloat16 h10, r10, h11, r11, h12, r12, h13, r13;
            bsplit(sacc[2 * ks][0], h00, r00);     bsplit(sacc[2 * ks][1], h01, r01);
            bsplit(sacc[2 * ks][2], h02, r02);     bsplit(sacc[2 * ks][3], h03, r03);
            bsplit(sacc[2 * ks + 1][0], h10, r10); bsplit(sacc[2 * ks + 1][1], h11, r11);
            bsplit(sacc[2 * ks + 1][2], h12, r12); bsplit(sacc[2 * ks + 1][3], h13, r13);
            uint32_t ph0 = bpack(h00, h01), ph1 = bpack(h02, h03);
            uint32_t ph2 = bpack(h10, h11), ph3 = bpack(h12, h13);
            uint32_t pl0 = bpack(r00, r01), pl1 = bpack(r02, r03);
            uint32_t pl2 = bpack(r10, r11), pl3 = bpack(r12, r13);
#pragma unroll
            for (int fn = 0; fn < 8; fn++) {
                int dd = fn * 8 + g;
                uint32_t vh0 = *(uint32_t*)&Vh[dd * BSTR + k0 + 2 * t];
                uint32_t vh1 = *(uint32_t*)&Vh[dd * BSTR + k0 + 2 * t + 8];
                uint32_t vl0 = *(uint32_t*)&Vl[dd * BSTR + k0 + 2 * t];
                uint32_t vl1 = *(uint32_t*)&Vl[dd * BSTR + k0 + 2 * t + 8];
                mma_bf16(O[fn], ph0, ph1, ph2, ph3, vh0, vh1);
                mma_bf16(O[fn], ph0, ph1, ph2, ph3, vl0, vl1);
                mma_bf16(O[fn], pl0, pl1, pl2, pl3, vh0, vh1);
            }
        }

        __syncthreads();   // all warps done reading buffer p
        int nt = tt + 2;
        if (nt < te) {
            load_tile_async(tid, col0, nt << 6, Khi_g, Klo_g, VThi_g, VTlo_g,
                            Kh_s + p * 64 * BSTR, Kl_s + p * 64 * BSTR,
                            Vh_s + p * 64 * BSTR, Vl_s + p * 64 * BSTR);
        }
        CP_COMMIT();   // keep group numbering aligned even when empty
    }

    // ---- store unnormalized partial O + (m, l) ----
#pragma unroll
    for (int fn = 0; fn < 8; fn++) {
        int col = fn * 8 + 2 * t;
        *(float2*)&g_Op[split][h][qb][row0][col]     = make_float2(O[fn][0], O[fn][1]);
        *(float2*)&g_Op[split][h][qb][row0 + 8][col] = make_float2(O[fn][2], O[fn][3]);
    }
    if (t == 0) {
        g_ml[split][h][qb][0][row0] = m0;     g_ml[split][h][qb][1][row0] = l0;
        g_ml[split][h][qb][0][row0 + 8] = m1; g_ml[split][h][qb][1][row0 + 8] = l1;
    }
}

// ---------------------------------------------------------------------------
// Combine the two key-split halves: Y = (e0*O0 + e1*O1) / (e0*l0 + e1*l1)
// ---------------------------------------------------------------------------
__global__ __launch_bounds__(256) void attn_combine_kernel(float* __restrict__ Y)
{
    int qb = blockIdx.x, h = blockIdx.y;
    int tid = threadIdx.x;
    int row = tid >> 1;            // 0..127
    int c0 = (tid & 1) << 5;       // 0 or 32

    float m0 = g_ml[0][h][qb][0][row], l0 = g_ml[0][h][qb][1][row];
    float m1 = g_ml[1][h][qb][0][row], l1 = g_ml[1][h][qb][1][row];
    float M = fmaxf(m0, m1);
    float e0 = __expf(m0 - M), e1 = __expf(m1 - M);
    float inv = 1.0f / (e0 * l0 + e1 * l1);
    float s0 = e0 * inv, s1 = e1 * inv;

    const float* O0 = &g_Op[0][h][qb][row][c0];
    const float* O1 = &g_Op[1][h][qb][row][c0];
    float* y = &Y[(size_t)((qb << 7) + row) * D_MOD + h * HDIM + c0];
#pragma unroll
    for (int c = 0; c < 32; c += 4) {
        float4 a = *(const float4*)&O0[c];
        float4 b = *(const float4*)&O1[c];
        float4 r;
        r.x = a.x * s0 + b.x * s1;
        r.y = a.y * s0 + b.y * s1;
        r.z = a.z * s0 + b.z * s1;
        r.w = a.w * s0 + b.w * s1;
        *(float4*)&y[c] = r;
    }
}

// ---------------------------------------------------------------------------
extern "C" void kernel_launch(void* const* d_in, const int* in_sizes, int n_in,
                              void* d_out, int out_size)
{
    (void)in_sizes; (void)n_in; (void)out_size;
    const float* l        = (const float*)d_in[0];
    const float* x        = (const float*)d_in[1];
    const float* W_attn_l = (const float*)d_in[2];
    const float* b_attn_l = (const float*)d_in[3];
    const float* W_attn_c = (const float*)d_in[4];
    const float* b_attn_c = (const float*)d_in[5];
    const float* W_q      = (const float*)d_in[6];
    const float* b_q      = (const float*)d_in[7];
    const float* W_proj   = (const float*)d_in[8];
    const float* b_proj   = (const float*)d_in[9];
    float* out = (float*)d_out;

    __nv_bfloat16 *Khi, *Klo, *VThi, *VTlo, *Qhi, *Qlo;
    float* Yp;
    cudaGetSymbolAddress((void**)&Khi, g_Khi);
    cudaGetSymbolAddress((void**)&Klo, g_Klo);
    cudaGetSymbolAddress((void**)&VThi, g_VThi);
    cudaGetSymbolAddress((void**)&VTlo, g_VTlo);
    cudaGetSymbolAddress((void**)&Qhi, g_Qhi);
    cudaGetSymbolAddress((void**)&Qlo, g_Qlo);
    cudaGetSymbolAddress((void**)&Yp, g_Y);

    dim3 blk(256);

    // kv_l -> K/VT rows 0:2048 ; kv_c -> rows 2048:4096 (bf16 hi/lo direct)
    gemm_tf32_bias_kernel<<<dim3(16, 16), blk>>>(l, W_attn_l, b_attn_l,
        nullptr, Khi, Klo, VThi, VTlo, 2048, 0);
    gemm_tf32_bias_kernel<<<dim3(16, 16), blk>>>(x, W_attn_c, b_attn_c,
        nullptr, Khi, Klo, VThi, VTlo, 2048, 2048);
    // q -> bf16 hi/lo natural
    gemm_tf32_bias_kernel<<<dim3(8, 16), blk>>>(x, W_q, b_q,
        nullptr, Qhi, Qlo, nullptr, nullptr, 1024, 0);

    // attention: 32 (qb-desc, split) x 16 heads; smem = 110592 B (2 CTA/SM)
    size_t smem = (size_t)(2 * 128 + 8 * 64) * BSTR * sizeof(__nv_bfloat16);
    cudaFuncSetAttribute(attn_mma_kernel, cudaFuncAttributeMaxDynamicSharedMemorySize, (int)smem);
    attn_mma_kernel<<<dim3(32, 16), blk, smem>>>(Qhi, Qlo, Khi, Klo, VThi, VTlo);

    // combine split halves -> Y
    attn_combine_kernel<<<dim3(16, 16), blk>>>(Yp);

    // output projection (fp32 path)
    gemm_tf32_bias_kernel<<<dim3(8, 16), blk>>>(Yp, W_proj, b_proj,
        out, nullptr, nullptr, nullptr, nullptr, 1024, 0);
}